// round 2
// baseline (speedup 1.0000x reference)
#include <cuda_runtime.h>
#include <math.h>

// Problem constants
// x: [8, 256, 64, 64]; WS=8 -> nwin=64, L=512 (seq), N=64 (batch), NH=8, hd=32
#define B_  8
#define C_  256
#define H_  64
#define W_  64
#define CR_ 64
#define L_  512
#define N_  64
#define NH_ 8
#define HD_ 32
#define NTOK (L_ * N_)          // 32768
#define QK_SCALE 0.17677669529663687f  // 1/sqrt(32)

// ---------------- scratch (device globals; no allocations allowed) -------------
__device__ float g_pooled[B_ * C_];
__device__ float g_ca[B_ * C_];
__device__ __align__(16) float g_xw[NTOK * C_];            // gated tokens [t][c], t = l*64+n
__device__ __align__(16) float g_q[N_ * NH_ * L_ * HD_];   // [n][h][l][d], scale folded in
__device__ __align__(16) float g_k[N_ * NH_ * L_ * HD_];
__device__ __align__(16) float g_v[N_ * NH_ * L_ * HD_];
__device__ __align__(16) float g_ao[NTOK * C_];            // attention out tokens [t][h*32+d]

// ---------------- fast exp on FMA/ALU pipes (avoid MUFU bottleneck) ------------
__device__ __forceinline__ float fast_exp(float x) {
    x = fmaxf(x, -87.0f);
    float y = x * 1.44269504088896341f;   // x * log2(e)
    float n = rintf(y);
    float f = y - n;                      // |f| <= 0.5
    float t = f * 0.6931471805599453f;    // f * ln2, |t| <= 0.347
    float p = 1.0f + t * (1.0f + t * (0.5f + t * (0.16666667f + t * (0.041666668f + t * 0.008333334f))));
    int e = (int)n;
    float s = __int_as_float((e + 127) << 23);
    return p * s;
}

// ---------------- 1) spatial mean pool -----------------------------------------
__global__ void pool_kernel(const float* __restrict__ x) {
    int bc = blockIdx.x;                       // 0..2047
    const float* p = x + (size_t)bc * (H_ * W_);
    float s = 0.f;
    for (int i = threadIdx.x; i < H_ * W_; i += 256) s += p[i];
    __shared__ float red[8];
    for (int o = 16; o; o >>= 1) s += __shfl_xor_sync(0xffffffffu, s, o);
    if ((threadIdx.x & 31) == 0) red[threadIdx.x >> 5] = s;
    __syncthreads();
    if (threadIdx.x < 8) {
        s = red[threadIdx.x];
        for (int o = 4; o; o >>= 1) s += __shfl_xor_sync(0xffu, s, o);
        if (threadIdx.x == 0) g_pooled[bc] = s * (1.0f / (H_ * W_));
    }
}

// ---------------- 2) SE gate MLP -----------------------------------------------
__global__ void se_kernel(const float* __restrict__ w1, const float* __restrict__ b1,
                          const float* __restrict__ w2, const float* __restrict__ b2) {
    __shared__ float h1s[B_ * CR_];            // 512
    int tid = threadIdx.x;                     // 512 threads
    {
        int b = tid >> 6, j = tid & 63;
        float s = b1[j];
        const float* pw = w1 + j * C_;
        const float* pp = g_pooled + b * C_;
        for (int c = 0; c < C_; c++) s += pp[c] * pw[c];
        h1s[tid] = fmaxf(s, 0.f);
    }
    __syncthreads();
    for (int i = tid; i < B_ * C_; i += 512) {
        int b = i >> 8, c = i & 255;
        float s = b2[c];
        const float* pw = w2 + c * CR_;
        const float* ph = h1s + b * CR_;
        for (int j = 0; j < CR_; j++) s += ph[j] * pw[j];
        g_ca[i] = 1.0f / (1.0f + expf(-s));
    }
}

// ---------------- 3) gather gated windows into token matrix XW -----------------
// XW[t][c] = x[b,c,hp,wp] * ca[b,c]; t = l*64+n, l = (hw*8+ww)*8+b, n = r*8+cc
__global__ void gather_kernel(const float* __restrict__ x) {
    int hp = blockIdx.x;        // 0..63
    int cg = blockIdx.y;        // 0..7 (32 channels each)
    int b  = blockIdx.z;        // 0..7
    __shared__ float tile[32][65];
    int tid = threadIdx.x;      // 256
    int wp = tid & 63, ci = tid >> 6;  // ci 0..3
    const float* base = x + (((size_t)(b * C_ + cg * 32)) << 12) + hp * W_;
#pragma unroll
    for (int i = 0; i < 8; i++) {
        int c = ci + i * 4;
        tile[c][wp] = base[((size_t)c << 12) + wp];
    }
    __syncthreads();
    int j = tid & 31, pi = tid >> 5;   // pi 0..7
    int hw = hp >> 3, r = hp & 7;
    float cav = g_ca[b * C_ + cg * 32 + j];
#pragma unroll
    for (int i = 0; i < 8; i++) {
        int wpp = pi + i * 8;
        int ww = wpp >> 3, cc = wpp & 7;
        int l = (hw * 8 + ww) * 8 + b;
        int t = l * 64 + (r * 8 + cc);
        g_xw[(size_t)t * C_ + cg * 32 + j] = tile[j][wpp] * cav;
    }
}

// ---------------- 4) QKV projection GEMM ---------------------------------------
// out[t][o] = sum_c XW[t][c] * W[o][c] + bias[o];  o<256->Q(*scale), <512->K, else V
// BM=128, BN=64, BK=16, 256 threads, 8x4 per thread
__global__ __launch_bounds__(256) void qkv_gemm_kernel(const float* __restrict__ W,
                                                       const float* __restrict__ bias) {
    __shared__ float As[16][132];
    __shared__ float Bs[16][68];
    int tid = threadIdx.x;
    int m0 = blockIdx.x * 128;
    int n0 = blockIdx.y * 64;
    int tx = tid & 15, ty = tid >> 4;
    float acc[8][4];
#pragma unroll
    for (int i = 0; i < 8; i++)
#pragma unroll
        for (int j = 0; j < 4; j++) acc[i][j] = 0.f;

    for (int k0 = 0; k0 < C_; k0 += 16) {
#pragma unroll
        for (int p = 0; p < 2; p++) {
            int f4i = tid + p * 256;
            int row = f4i >> 2, kq = f4i & 3;
            float4 v = *(const float4*)&g_xw[(size_t)(m0 + row) * C_ + k0 + kq * 4];
            As[kq * 4 + 0][row] = v.x; As[kq * 4 + 1][row] = v.y;
            As[kq * 4 + 2][row] = v.z; As[kq * 4 + 3][row] = v.w;
        }
        {
            int row = tid >> 2, kq = tid & 3;
            float4 v = *(const float4*)&W[(size_t)(n0 + row) * C_ + k0 + kq * 4];
            Bs[kq * 4 + 0][row] = v.x; Bs[kq * 4 + 1][row] = v.y;
            Bs[kq * 4 + 2][row] = v.z; Bs[kq * 4 + 3][row] = v.w;
        }
        __syncthreads();
#pragma unroll
        for (int kk = 0; kk < 16; kk++) {
            float a[8], b[4];
            *(float4*)&a[0] = *(float4*)&As[kk][ty * 8];
            *(float4*)&a[4] = *(float4*)&As[kk][ty * 8 + 4];
            *(float4*)&b[0] = *(float4*)&Bs[kk][tx * 4];
#pragma unroll
            for (int i = 0; i < 8; i++)
#pragma unroll
                for (int j = 0; j < 4; j++) acc[i][j] += a[i] * b[j];
        }
        __syncthreads();
    }
#pragma unroll
    for (int i = 0; i < 8; i++) {
        int t = m0 + ty * 8 + i;
        int l = t >> 6, n = t & 63;
#pragma unroll
        for (int j = 0; j < 4; j++) {
            int o = n0 + tx * 4 + j;
            float v = acc[i][j] + bias[o];
            int oc = o & 255;
            int h = oc >> 5, d = oc & 31;
            size_t idx = ((size_t)((n * NH_ + h) * L_ + l)) * HD_ + d;
            if (o < 256)      g_q[idx] = v * QK_SCALE;
            else if (o < 512) g_k[idx] = v;
            else              g_v[idx] = v;
        }
    }
}

// ---------------- 5) attention (flash-style, per (n,h,q-tile)) -----------------
__global__ __launch_bounds__(128) void attn_kernel() {
    int qt = blockIdx.x;   // 0..7
    int h  = blockIdx.y;   // 0..7
    int n  = blockIdx.z;   // 0..63
    const float* Qb = g_q + ((size_t)(n * NH_ + h)) * L_ * HD_;
    const float* Kb = g_k + ((size_t)(n * NH_ + h)) * L_ * HD_;
    const float* Vb = g_v + ((size_t)(n * NH_ + h)) * L_ * HD_;
    __shared__ float Qs[64][33];
    __shared__ float Ks[64][33];
    __shared__ float Vs[64][36];
    __shared__ float Ps[64][65];
    int tid = threadIdx.x;
    int tx = tid & 7, ty = tid >> 3;   // rows ty*4.., cols tx*8.. (S) / d = tx*4 (PV)

    for (int i = tid; i < 64 * 32; i += 128) {
        int r = i >> 5, k = i & 31;
        Qs[r][k] = Qb[(qt * 64 + r) * HD_ + k];
    }
    float m_old[4], lsum[4], acc[4][4];
#pragma unroll
    for (int i = 0; i < 4; i++) {
        m_old[i] = -1e30f; lsum[i] = 0.f;
#pragma unroll
        for (int j = 0; j < 4; j++) acc[i][j] = 0.f;
    }

    for (int kt = 0; kt < 8; kt++) {
        for (int i = tid; i < 64 * 32; i += 128) {
            int r = i >> 5, k = i & 31;
            Ks[r][k] = Kb[(kt * 64 + r) * HD_ + k];
        }
        const float4* Vg = (const float4*)(Vb + (size_t)kt * 64 * HD_);
        for (int i = tid; i < 512; i += 128) {
            int r = i >> 3, kq = i & 7;
            *(float4*)&Vs[r][kq * 4] = Vg[i];
        }
        __syncthreads();

        float s[4][8];
#pragma unroll
        for (int i = 0; i < 4; i++)
#pragma unroll
            for (int j = 0; j < 8; j++) s[i][j] = 0.f;
#pragma unroll
        for (int k = 0; k < 32; k++) {
            float a[4], b[8];
#pragma unroll
            for (int i = 0; i < 4; i++) a[i] = Qs[ty * 4 + i][k];
#pragma unroll
            for (int j = 0; j < 8; j++) b[j] = Ks[tx * 8 + j][k];
#pragma unroll
            for (int i = 0; i < 4; i++)
#pragma unroll
                for (int j = 0; j < 8; j++) s[i][j] += a[i] * b[j];
        }
#pragma unroll
        for (int i = 0; i < 4; i++) {
            float mloc = s[i][0];
#pragma unroll
            for (int j = 1; j < 8; j++) mloc = fmaxf(mloc, s[i][j]);
            for (int o = 1; o < 8; o <<= 1) mloc = fmaxf(mloc, __shfl_xor_sync(0xffffffffu, mloc, o));
            float mnew = fmaxf(m_old[i], mloc);
            float alpha = fast_exp(m_old[i] - mnew);
            float psum = 0.f;
#pragma unroll
            for (int j = 0; j < 8; j++) { float p = fast_exp(s[i][j] - mnew); s[i][j] = p; psum += p; }
            for (int o = 1; o < 8; o <<= 1) psum += __shfl_xor_sync(0xffffffffu, psum, o);
            lsum[i] = lsum[i] * alpha + psum;
            m_old[i] = mnew;
#pragma unroll
            for (int j = 0; j < 4; j++) acc[i][j] *= alpha;
#pragma unroll
            for (int j = 0; j < 8; j++) Ps[ty * 4 + i][tx * 8 + j] = s[i][j];
        }
        __syncthreads();
#pragma unroll 4
        for (int kv = 0; kv < 64; kv++) {
            float4 v = *(const float4*)&Vs[kv][tx * 4];
            float p0 = Ps[ty * 4 + 0][kv];
            float p1 = Ps[ty * 4 + 1][kv];
            float p2 = Ps[ty * 4 + 2][kv];
            float p3 = Ps[ty * 4 + 3][kv];
            acc[0][0] += p0 * v.x; acc[0][1] += p0 * v.y; acc[0][2] += p0 * v.z; acc[0][3] += p0 * v.w;
            acc[1][0] += p1 * v.x; acc[1][1] += p1 * v.y; acc[1][2] += p1 * v.z; acc[1][3] += p1 * v.w;
            acc[2][0] += p2 * v.x; acc[2][1] += p2 * v.y; acc[2][2] += p2 * v.z; acc[2][3] += p2 * v.w;
            acc[3][0] += p3 * v.x; acc[3][1] += p3 * v.y; acc[3][2] += p3 * v.z; acc[3][3] += p3 * v.w;
        }
        __syncthreads();
    }
#pragma unroll
    for (int i = 0; i < 4; i++) {
        int row = ty * 4 + i;
        int l = qt * 64 + row;
        float inv = 1.0f / lsum[i];
        size_t base = ((size_t)(l * 64 + n)) * C_ + h * HD_ + tx * 4;
        float4 o4;
        o4.x = acc[i][0] * inv; o4.y = acc[i][1] * inv;
        o4.z = acc[i][2] * inv; o4.w = acc[i][3] * inv;
        *(float4*)&g_ao[base] = o4;
    }
}

// ---------------- 6) out-proj GEMM + gated residual epilogue -------------------
// out[b,c,hq=win,wq=n] = x[b,c,win,wq]*ca[b,c] + (AO @ Wout^T + bo)[t=(win*8+b)*64+wq][c]
__global__ __launch_bounds__(256) void outproj_kernel(const float* __restrict__ Wout,
                                                      const float* __restrict__ bias,
                                                      const float* __restrict__ x,
                                                      float* __restrict__ out) {
    __shared__ float As[16][132];
    __shared__ float Bs[16][68];
    __shared__ float Ts[128][65];
    int tid = threadIdx.x;
    int m0 = blockIdx.x * 128;
    int n0 = blockIdx.y * 64;
    int tx = tid & 15, ty = tid >> 4;
    float acc[8][4];
#pragma unroll
    for (int i = 0; i < 8; i++)
#pragma unroll
        for (int j = 0; j < 4; j++) acc[i][j] = 0.f;

    for (int k0 = 0; k0 < C_; k0 += 16) {
#pragma unroll
        for (int p = 0; p < 2; p++) {
            int f4i = tid + p * 256;
            int row = f4i >> 2, kq = f4i & 3;
            float4 v = *(const float4*)&g_ao[(size_t)(m0 + row) * C_ + k0 + kq * 4];
            As[kq * 4 + 0][row] = v.x; As[kq * 4 + 1][row] = v.y;
            As[kq * 4 + 2][row] = v.z; As[kq * 4 + 3][row] = v.w;
        }
        {
            int row = tid >> 2, kq = tid & 3;
            float4 v = *(const float4*)&Wout[(size_t)(n0 + row) * C_ + k0 + kq * 4];
            Bs[kq * 4 + 0][row] = v.x; Bs[kq * 4 + 1][row] = v.y;
            Bs[kq * 4 + 2][row] = v.z; Bs[kq * 4 + 3][row] = v.w;
        }
        __syncthreads();
#pragma unroll
        for (int kk = 0; kk < 16; kk++) {
            float a[8], b[4];
            *(float4*)&a[0] = *(float4*)&As[kk][ty * 8];
            *(float4*)&a[4] = *(float4*)&As[kk][ty * 8 + 4];
            *(float4*)&b[0] = *(float4*)&Bs[kk][tx * 4];
#pragma unroll
            for (int i = 0; i < 8; i++)
#pragma unroll
                for (int j = 0; j < 4; j++) acc[i][j] += a[i] * b[j];
        }
        __syncthreads();
    }
    // stage with bias
#pragma unroll
    for (int i = 0; i < 8; i++)
#pragma unroll
        for (int j = 0; j < 4; j++)
            Ts[ty * 8 + i][tx * 4 + j] = acc[i][j] + bias[n0 + tx * 4 + j];
    __syncthreads();

    int wq = tid & 63, qq = tid >> 6;  // qq 0..3
    int l0 = m0 >> 6;
#pragma unroll
    for (int h2 = 0; h2 < 2; h2++) {
        int l = l0 + h2;
        int win = l >> 3, b = l & 7;
#pragma unroll
        for (int ci = 0; ci < 16; ci++) {
            int c_local = ci * 4 + qq;
            int c = n0 + c_local;
            float v = Ts[h2 * 64 + wq][c_local];
            size_t idx = (((size_t)(b * C_ + c)) * H_ + win) * W_ + wq;
            out[idx] = x[idx] * g_ca[b * C_ + c] + v;
        }
    }
}

// ---------------- launch --------------------------------------------------------
extern "C" void kernel_launch(void* const* d_in, const int* in_sizes, int n_in,
                              void* d_out, int out_size) {
    const float* x     = (const float*)d_in[0];
    const float* ca_w1 = (const float*)d_in[1];
    const float* ca_b1 = (const float*)d_in[2];
    const float* ca_w2 = (const float*)d_in[3];
    const float* ca_b2 = (const float*)d_in[4];
    const float* in_w  = (const float*)d_in[5];
    const float* in_b  = (const float*)d_in[6];
    const float* out_w = (const float*)d_in[7];
    const float* out_b = (const float*)d_in[8];
    float* out = (float*)d_out;

    pool_kernel<<<B_ * C_, 256>>>(x);
    se_kernel<<<1, 512>>>(ca_w1, ca_b1, ca_w2, ca_b2);
    gather_kernel<<<dim3(64, 8, 8), 256>>>(x);
    qkv_gemm_kernel<<<dim3(NTOK / 128, 12), 256>>>(in_w, in_b);
    attn_kernel<<<dim3(8, 8, 64), 128>>>();
    outproj_kernel<<<dim3(NTOK / 128, 4), 256>>>(out_w, out_b, x, out);
}

// round 4
// speedup vs baseline: 1.1871x; 1.1871x over previous
#include <cuda_runtime.h>
#include <cuda_bf16.h>
#include <cstdint>
#include <math.h>

// Problem constants
#define B_  8
#define C_  256
#define H_  64
#define W_  64
#define CR_ 64
#define L_  512
#define N_  64
#define NH_ 8
#define HD_ 32
#define NTOK (L_ * N_)          // 32768
#define QK_SCALE 0.17677669529663687f  // 1/sqrt(32)

// ---------------- scratch (device globals; no allocations allowed) -------------
__device__ float g_pooled[B_ * C_];
__device__ float g_ca[B_ * C_];
__device__ __align__(16) __nv_bfloat16 g_xw_hi[NTOK * C_];   // gated tokens [t][c]
__device__ __align__(16) __nv_bfloat16 g_xw_lo[NTOK * C_];
__device__ __align__(16) __nv_bfloat16 g_wqkv_hi[3 * C_ * C_];
__device__ __align__(16) __nv_bfloat16 g_wqkv_lo[3 * C_ * C_];
__device__ __align__(16) __nv_bfloat16 g_wout_hi[C_ * C_];
__device__ __align__(16) __nv_bfloat16 g_wout_lo[C_ * C_];
__device__ __align__(16) float g_q[N_ * NH_ * L_ * HD_];   // [n][h][l][d], scale folded in
__device__ __align__(16) float g_k[N_ * NH_ * L_ * HD_];
__device__ __align__(16) float g_v[N_ * NH_ * L_ * HD_];
__device__ __align__(16) __nv_bfloat16 g_ao_hi[NTOK * C_]; // attn out [t][h*32+d]
__device__ __align__(16) __nv_bfloat16 g_ao_lo[NTOK * C_];

// ---------------- warp MMA helpers (HMMA via mma.sync, legal on sm_103) --------
__device__ __forceinline__ uint32_t smem_u32(const void* p) {
    uint32_t a;
    asm("{ .reg .u64 t; cvta.to.shared.u64 t, %1; cvt.u32.u64 %0, t; }" : "=r"(a) : "l"(p));
    return a;
}
__device__ __forceinline__ void ldsm_x4(uint32_t& r0, uint32_t& r1, uint32_t& r2, uint32_t& r3,
                                        uint32_t addr) {
    asm volatile("ldmatrix.sync.aligned.m8n8.x4.shared.b16 {%0,%1,%2,%3}, [%4];"
                 : "=r"(r0), "=r"(r1), "=r"(r2), "=r"(r3) : "r"(addr));
}
__device__ __forceinline__ void mma_bf16(float* c, const uint32_t* a, const uint32_t* b) {
    asm volatile("mma.sync.aligned.m16n8k16.row.col.f32.bf16.bf16.f32 "
                 "{%0,%1,%2,%3}, {%4,%5,%6,%7}, {%8,%9}, {%0,%1,%2,%3};"
                 : "+f"(c[0]), "+f"(c[1]), "+f"(c[2]), "+f"(c[3])
                 : "r"(a[0]), "r"(a[1]), "r"(a[2]), "r"(a[3]), "r"(b[0]), "r"(b[1]));
}

#define BK 32
#define AST 40   // padded smem row stride in bf16 (80B: conflict-free ldmatrix)

// ---------------- fast exp on FMA/ALU pipes -------------------------------------
__device__ __forceinline__ float fast_exp(float x) {
    x = fmaxf(x, -87.0f);
    float y = x * 1.44269504088896341f;
    float n = rintf(y);
    float f = y - n;
    float t = f * 0.6931471805599453f;
    float p = 1.0f + t * (1.0f + t * (0.5f + t * (0.16666667f + t * (0.041666668f + t * 0.008333334f))));
    int e = (int)n;
    float s = __int_as_float((e + 127) << 23);
    return p * s;
}

__device__ __forceinline__ void split_bf16(float v, __nv_bfloat16& hi, __nv_bfloat16& lo) {
    hi = __float2bfloat16_rn(v);
    lo = __float2bfloat16_rn(v - __bfloat162float(hi));
}

// ---------------- 0) weight conversion f32 -> bf16 hi/lo ------------------------
__global__ void convert_w_kernel(const float* __restrict__ in_w, const float* __restrict__ out_w) {
    int i = blockIdx.x * 256 + threadIdx.x;
    if (i < 3 * C_ * C_) {
        __nv_bfloat16 h, l;
        split_bf16(in_w[i], h, l);
        g_wqkv_hi[i] = h; g_wqkv_lo[i] = l;
    }
    if (i < C_ * C_) {
        __nv_bfloat16 h, l;
        split_bf16(out_w[i], h, l);
        g_wout_hi[i] = h; g_wout_lo[i] = l;
    }
}

// ---------------- 1) spatial mean pool -----------------------------------------
__global__ void pool_kernel(const float* __restrict__ x) {
    int bc = blockIdx.x;
    const float* p = x + (size_t)bc * (H_ * W_);
    float s = 0.f;
    for (int i = threadIdx.x; i < H_ * W_; i += 256) s += p[i];
    __shared__ float red[8];
    for (int o = 16; o; o >>= 1) s += __shfl_xor_sync(0xffffffffu, s, o);
    if ((threadIdx.x & 31) == 0) red[threadIdx.x >> 5] = s;
    __syncthreads();
    if (threadIdx.x < 8) {
        s = red[threadIdx.x];
        for (int o = 4; o; o >>= 1) s += __shfl_xor_sync(0xffu, s, o);
        if (threadIdx.x == 0) g_pooled[bc] = s * (1.0f / (H_ * W_));
    }
}

// ---------------- 2) SE gate MLP -----------------------------------------------
__global__ void se_kernel(const float* __restrict__ w1, const float* __restrict__ b1,
                          const float* __restrict__ w2, const float* __restrict__ b2) {
    __shared__ float h1s[B_ * CR_];
    int tid = threadIdx.x;
    {
        int b = tid >> 6, j = tid & 63;
        float s = b1[j];
        const float* pw = w1 + j * C_;
        const float* pp = g_pooled + b * C_;
        for (int c = 0; c < C_; c++) s += pp[c] * pw[c];
        h1s[tid] = fmaxf(s, 0.f);
    }
    __syncthreads();
    for (int i = tid; i < B_ * C_; i += 512) {
        int b = i >> 8, c = i & 255;
        float s = b2[c];
        const float* pw = w2 + c * CR_;
        const float* ph = h1s + b * CR_;
        for (int j = 0; j < CR_; j++) s += ph[j] * pw[j];
        g_ca[i] = 1.0f / (1.0f + expf(-s));
    }
}

// ---------------- 3) gather gated windows into bf16 hi/lo token matrix ---------
__global__ void gather_kernel(const float* __restrict__ x) {
    int hp = blockIdx.x;
    int cg = blockIdx.y;
    int b  = blockIdx.z;
    __shared__ float tile[32][65];
    int tid = threadIdx.x;
    int wp = tid & 63, ci = tid >> 6;
    const float* base = x + (((size_t)(b * C_ + cg * 32)) << 12) + hp * W_;
#pragma unroll
    for (int i = 0; i < 8; i++) {
        int c = ci + i * 4;
        tile[c][wp] = base[((size_t)c << 12) + wp];
    }
    __syncthreads();
    int j = tid & 31, pi = tid >> 5;
    int hw = hp >> 3, r = hp & 7;
    float cav = g_ca[b * C_ + cg * 32 + j];
#pragma unroll
    for (int i = 0; i < 8; i++) {
        int wpp = pi + i * 8;
        int ww = wpp >> 3, cc = wpp & 7;
        int l = (hw * 8 + ww) * 8 + b;
        int t = l * 64 + (r * 8 + cc);
        float v = tile[j][wpp] * cav;
        __nv_bfloat16 h, lo;
        split_bf16(v, h, lo);
        size_t idx = (size_t)t * C_ + cg * 32 + j;
        g_xw_hi[idx] = h;
        g_xw_lo[idx] = lo;
    }
}

// ---------------- shared mainloop: bf16x3 HMMA GEMM ----------------------------
// acc[mt][nt][4] for a 128x64 block tile; 8 warps as 2(M) x 4(N), warp = 64x16.
struct GemmSmem {
    __nv_bfloat16 Ah[128][AST];
    __nv_bfloat16 Al[128][AST];
    __nv_bfloat16 Bh[64][AST];
    __nv_bfloat16 Bl[64][AST];
};

__device__ __forceinline__ void gemm_mainloop(GemmSmem& sm,
    const __nv_bfloat16* __restrict__ Ah, const __nv_bfloat16* __restrict__ Al,
    const __nv_bfloat16* __restrict__ Bh, const __nv_bfloat16* __restrict__ Bl,
    int m0, int n0, float acc[4][2][4]) {
    int tid = threadIdx.x;
    int lane = tid & 31, wid = tid >> 5;
    int wm = wid & 1, wn = wid >> 1;
    int lrow = lane & 15, lkq = lane >> 4;

    uint32_t sAh0 = smem_u32(&sm.Ah[0][0]);
    uint32_t sAl0 = smem_u32(&sm.Al[0][0]);
    uint32_t sBh0 = smem_u32(&sm.Bh[0][0]);
    uint32_t sBl0 = smem_u32(&sm.Bl[0][0]);

    for (int chunk = 0; chunk < 8; chunk++) {
        int k0 = chunk * BK;
#pragma unroll
        for (int p = 0; p < 2; p++) {
            int i = tid + p * 256;
            int row = i >> 2, q = i & 3;
            size_t gi = (size_t)(m0 + row) * C_ + k0 + q * 8;
            *(uint4*)&sm.Ah[row][q * 8] = *(const uint4*)(Ah + gi);
            *(uint4*)&sm.Al[row][q * 8] = *(const uint4*)(Al + gi);
        }
        {
            int row = tid >> 2, q = tid & 3;
            size_t gi = (size_t)(n0 + row) * C_ + k0 + q * 8;
            *(uint4*)&sm.Bh[row][q * 8] = *(const uint4*)(Bh + gi);
            *(uint4*)&sm.Bl[row][q * 8] = *(const uint4*)(Bl + gi);
        }
        __syncthreads();

#pragma unroll
        for (int ks = 0; ks < 2; ks++) {
            int kk = ks * 16 + lkq * 8;
            uint32_t ah[4][4], al[4][4], bh[4], bl[4];
#pragma unroll
            for (int mt = 0; mt < 4; mt++) {
                int row = wm * 64 + mt * 16 + lrow;
                uint32_t off = (uint32_t)(row * AST + kk) * 2;
                ldsm_x4(ah[mt][0], ah[mt][1], ah[mt][2], ah[mt][3], sAh0 + off);
                ldsm_x4(al[mt][0], al[mt][1], al[mt][2], al[mt][3], sAl0 + off);
            }
            {
                int row = wn * 16 + lrow;
                uint32_t off = (uint32_t)(row * AST + kk) * 2;
                ldsm_x4(bh[0], bh[1], bh[2], bh[3], sBh0 + off);
                ldsm_x4(bl[0], bl[1], bl[2], bl[3], sBl0 + off);
            }
            // b fragments: tile0 = {r0,r2}, tile1 = {r1,r3}
            uint32_t b0h[2] = { bh[0], bh[2] }, b1h[2] = { bh[1], bh[3] };
            uint32_t b0l[2] = { bl[0], bl[2] }, b1l[2] = { bl[1], bl[3] };
#pragma unroll
            for (int mt = 0; mt < 4; mt++) {
                mma_bf16(acc[mt][0], ah[mt], b0h);
                mma_bf16(acc[mt][1], ah[mt], b1h);
                mma_bf16(acc[mt][0], ah[mt], b0l);
                mma_bf16(acc[mt][1], ah[mt], b1l);
                mma_bf16(acc[mt][0], al[mt], b0h);
                mma_bf16(acc[mt][1], al[mt], b1h);
            }
        }
        __syncthreads();
    }
}

// ---------------- 4) QKV projection (HMMA bf16x3) ------------------------------
__global__ __launch_bounds__(256) void qkv_mma_kernel(const float* __restrict__ bias) {
    __shared__ GemmSmem sm;
    int m0 = blockIdx.x * 128;
    int n0 = blockIdx.y * 64;
    float acc[4][2][4];
#pragma unroll
    for (int mt = 0; mt < 4; mt++)
#pragma unroll
        for (int nt = 0; nt < 2; nt++)
#pragma unroll
            for (int j = 0; j < 4; j++) acc[mt][nt][j] = 0.f;

    gemm_mainloop(sm, g_xw_hi, g_xw_lo, g_wqkv_hi, g_wqkv_lo, m0, n0, acc);

    int lane = threadIdx.x & 31, wid = threadIdx.x >> 5;
    int wm = wid & 1, wn = wid >> 1;
    int sec = n0 >> 8;                 // 0=Q, 1=K, 2=V
    float* dstb = (sec == 0) ? g_q : (sec == 1) ? g_k : g_v;
    float scale = (sec == 0) ? QK_SCALE : 1.0f;
    int l = (m0 >> 6) + wm;
    int r = lane >> 2;
#pragma unroll
    for (int mt = 0; mt < 4; mt++) {
#pragma unroll
        for (int nt = 0; nt < 2; nt++) {
            int col = n0 + wn * 16 + nt * 8 + (lane & 3) * 2;
            int oc = col & 255;
            int h = oc >> 5, d = oc & 31;
            float2 bi = *(const float2*)&bias[col];
#pragma unroll
            for (int half = 0; half < 2; half++) {
                int n = mt * 16 + r + half * 8;
                float2 v;
                v.x = (acc[mt][nt][half * 2 + 0] + bi.x) * scale;
                v.y = (acc[mt][nt][half * 2 + 1] + bi.y) * scale;
                *(float2*)&dstb[(((size_t)(n * NH_ + h) * L_ + l) << 5) + d] = v;
            }
        }
    }
}

// ---------------- 5) attention (flash-style SIMT) ------------------------------
__global__ __launch_bounds__(128) void attn_kernel() {
    int qt = blockIdx.x;
    int h  = blockIdx.y;
    int n  = blockIdx.z;
    const float* Qb = g_q + ((size_t)(n * NH_ + h)) * L_ * HD_;
    const float* Kb = g_k + ((size_t)(n * NH_ + h)) * L_ * HD_;
    const float* Vb = g_v + ((size_t)(n * NH_ + h)) * L_ * HD_;
    __shared__ float Qs[64][33];
    __shared__ float Ks[64][33];
    __shared__ float Vs[64][36];
    __shared__ float Ps[64][65];
    int tid = threadIdx.x;
    int tx = tid & 7, ty = tid >> 3;

    for (int i = tid; i < 64 * 32; i += 128) {
        int r = i >> 5, k = i & 31;
        Qs[r][k] = Qb[(qt * 64 + r) * HD_ + k];
    }
    float m_old[4], lsum[4], acc[4][4];
#pragma unroll
    for (int i = 0; i < 4; i++) {
        m_old[i] = -1e30f; lsum[i] = 0.f;
#pragma unroll
        for (int j = 0; j < 4; j++) acc[i][j] = 0.f;
    }

    for (int kt = 0; kt < 8; kt++) {
        for (int i = tid; i < 64 * 32; i += 128) {
            int r = i >> 5, k = i & 31;
            Ks[r][k] = Kb[(kt * 64 + r) * HD_ + k];
        }
        const float4* Vg = (const float4*)(Vb + (size_t)kt * 64 * HD_);
        for (int i = tid; i < 512; i += 128) {
            int r = i >> 3, kq = i & 7;
            *(float4*)&Vs[r][kq * 4] = Vg[i];
        }
        __syncthreads();

        float s[4][8];
#pragma unroll
        for (int i = 0; i < 4; i++)
#pragma unroll
            for (int j = 0; j < 8; j++) s[i][j] = 0.f;
#pragma unroll
        for (int k = 0; k < 32; k++) {
            float a[4], b[8];
#pragma unroll
            for (int i = 0; i < 4; i++) a[i] = Qs[ty * 4 + i][k];
#pragma unroll
            for (int j = 0; j < 8; j++) b[j] = Ks[tx * 8 + j][k];
#pragma unroll
            for (int i = 0; i < 4; i++)
#pragma unroll
                for (int j = 0; j < 8; j++) s[i][j] += a[i] * b[j];
        }
#pragma unroll
        for (int i = 0; i < 4; i++) {
            float mloc = s[i][0];
#pragma unroll
            for (int j = 1; j < 8; j++) mloc = fmaxf(mloc, s[i][j]);
            for (int o = 1; o < 8; o <<= 1) mloc = fmaxf(mloc, __shfl_xor_sync(0xffffffffu, mloc, o));
            float mnew = fmaxf(m_old[i], mloc);
            float alpha = fast_exp(m_old[i] - mnew);
            float psum = 0.f;
#pragma unroll
            for (int j = 0; j < 8; j++) { float p = fast_exp(s[i][j] - mnew); s[i][j] = p; psum += p; }
            for (int o = 1; o < 8; o <<= 1) psum += __shfl_xor_sync(0xffffffffu, psum, o);
            lsum[i] = lsum[i] * alpha + psum;
            m_old[i] = mnew;
#pragma unroll
            for (int j = 0; j < 4; j++) acc[i][j] *= alpha;
#pragma unroll
            for (int j = 0; j < 8; j++) Ps[ty * 4 + i][tx * 8 + j] = s[i][j];
        }
        __syncthreads();
#pragma unroll 4
        for (int kv = 0; kv < 64; kv++) {
            float4 v = *(const float4*)&Vs[kv][tx * 4];
            float p0 = Ps[ty * 4 + 0][kv];
            float p1 = Ps[ty * 4 + 1][kv];
            float p2 = Ps[ty * 4 + 2][kv];
            float p3 = Ps[ty * 4 + 3][kv];
            acc[0][0] += p0 * v.x; acc[0][1] += p0 * v.y; acc[0][2] += p0 * v.z; acc[0][3] += p0 * v.w;
            acc[1][0] += p1 * v.x; acc[1][1] += p1 * v.y; acc[1][2] += p1 * v.z; acc[1][3] += p1 * v.w;
            acc[2][0] += p2 * v.x; acc[2][1] += p2 * v.y; acc[2][2] += p2 * v.z; acc[2][3] += p2 * v.w;
            acc[3][0] += p3 * v.x; acc[3][1] += p3 * v.y; acc[3][2] += p3 * v.z; acc[3][3] += p3 * v.w;
        }
        __syncthreads();
    }
#pragma unroll
    for (int i = 0; i < 4; i++) {
        int row = ty * 4 + i;
        int l = qt * 64 + row;
        float inv = 1.0f / lsum[i];
        size_t base = ((size_t)(l * 64 + n)) * C_ + h * HD_ + tx * 4;
        __nv_bfloat162 hi2[2], lo2[2];
#pragma unroll
        for (int p = 0; p < 2; p++) {
            float v0 = acc[i][p * 2 + 0] * inv;
            float v1 = acc[i][p * 2 + 1] * inv;
            __nv_bfloat16 h0, l0, h1, l1;
            split_bf16(v0, h0, l0);
            split_bf16(v1, h1, l1);
            hi2[p] = __nv_bfloat162(h0, h1);
            lo2[p] = __nv_bfloat162(l0, l1);
        }
        *(uint2*)(g_ao_hi + base) = *(uint2*)hi2;
        *(uint2*)(g_ao_lo + base) = *(uint2*)lo2;
    }
}

// ---------------- 6) out-proj (HMMA bf16x3) + gated residual -------------------
__global__ __launch_bounds__(256) void outproj_mma_kernel(const float* __restrict__ bias,
                                                          const float* __restrict__ x,
                                                          float* __restrict__ out) {
    __shared__ GemmSmem sm;
    int m0 = blockIdx.x * 128;
    int n0 = blockIdx.y * 64;
    float acc[4][2][4];
#pragma unroll
    for (int mt = 0; mt < 4; mt++)
#pragma unroll
        for (int nt = 0; nt < 2; nt++)
#pragma unroll
            for (int j = 0; j < 4; j++) acc[mt][nt][j] = 0.f;

    gemm_mainloop(sm, g_ao_hi, g_ao_lo, g_wout_hi, g_wout_lo, m0, n0, acc);

    int lane = threadIdx.x & 31, wid = threadIdx.x >> 5;
    int wm = wid & 1, wn = wid >> 1;
    int l = (m0 >> 6) + wm;
    int win = l >> 3, b = l & 7;
    int r = lane >> 2;
#pragma unroll
    for (int mt = 0; mt < 4; mt++) {
#pragma unroll
        for (int nt = 0; nt < 2; nt++) {
            int col = n0 + wn * 16 + nt * 8 + (lane & 3) * 2;
            float2 bi = *(const float2*)&bias[col];
            float ca0 = g_ca[b * C_ + col];
            float ca1 = g_ca[b * C_ + col + 1];
#pragma unroll
            for (int half = 0; half < 2; half++) {
                int wq = mt * 16 + r + half * 8;
                size_t idx0 = (((size_t)(b * C_ + col)) * H_ + win) * W_ + wq;
                size_t idx1 = idx0 + (size_t)H_ * W_;
                out[idx0] = x[idx0] * ca0 + acc[mt][nt][half * 2 + 0] + bi.x;
                out[idx1] = x[idx1] * ca1 + acc[mt][nt][half * 2 + 1] + bi.y;
            }
        }
    }
}

// ---------------- launch --------------------------------------------------------
extern "C" void kernel_launch(void* const* d_in, const int* in_sizes, int n_in,
                              void* d_out, int out_size) {
    const float* x     = (const float*)d_in[0];
    const float* ca_w1 = (const float*)d_in[1];
    const float* ca_b1 = (const float*)d_in[2];
    const float* ca_w2 = (const float*)d_in[3];
    const float* ca_b2 = (const float*)d_in[4];
    const float* in_w  = (const float*)d_in[5];
    const float* in_b  = (const float*)d_in[6];
    const float* out_w = (const float*)d_in[7];
    const float* out_b = (const float*)d_in[8];
    float* out = (float*)d_out;

    convert_w_kernel<<<(3 * C_ * C_ + 255) / 256, 256>>>(in_w, out_w);
    pool_kernel<<<B_ * C_, 256>>>(x);
    se_kernel<<<1, 512>>>(ca_w1, ca_b1, ca_w2, ca_b2);
    gather_kernel<<<dim3(64, 8, 8), 256>>>(x);
    qkv_mma_kernel<<<dim3(NTOK / 128, 12), 256>>>(in_b);
    attn_kernel<<<dim3(8, 8, 64), 128>>>();
    outproj_mma_kernel<<<dim3(NTOK / 128, 4), 256>>>(out_b, x, out);
}

// round 5
// speedup vs baseline: 1.8831x; 1.5863x over previous
#include <cuda_runtime.h>
#include <cuda_bf16.h>
#include <cstdint>
#include <math.h>

// Problem constants
#define B_  8
#define C_  256
#define H_  64
#define W_  64
#define CR_ 64
#define L_  512
#define N_  64
#define NH_ 8
#define HD_ 32
#define NTOK (L_ * N_)          // 32768
#define QK_SCALE 0.17677669529663687f  // 1/sqrt(32)

// ---------------- scratch (device globals; no allocations allowed) -------------
__device__ float g_pooled[B_ * C_];
__device__ float g_ca[B_ * C_];
__device__ __align__(16) __nv_bfloat16 g_xw_hi[NTOK * C_];   // gated tokens [t][c]
__device__ __align__(16) __nv_bfloat16 g_xw_lo[NTOK * C_];
__device__ __align__(16) __nv_bfloat16 g_wqkv_hi[3 * C_ * C_];
__device__ __align__(16) __nv_bfloat16 g_wqkv_lo[3 * C_ * C_];
__device__ __align__(16) __nv_bfloat16 g_wout_hi[C_ * C_];
__device__ __align__(16) __nv_bfloat16 g_wout_lo[C_ * C_];
// Q/K/V as bf16 hi/lo, layout [n][h][l][d]
__device__ __align__(16) __nv_bfloat16 g_qh[N_ * NH_ * L_ * HD_];
__device__ __align__(16) __nv_bfloat16 g_ql[N_ * NH_ * L_ * HD_];
__device__ __align__(16) __nv_bfloat16 g_kh[N_ * NH_ * L_ * HD_];
__device__ __align__(16) __nv_bfloat16 g_kl[N_ * NH_ * L_ * HD_];
__device__ __align__(16) __nv_bfloat16 g_vh[N_ * NH_ * L_ * HD_];
__device__ __align__(16) __nv_bfloat16 g_vl[N_ * NH_ * L_ * HD_];
__device__ __align__(16) __nv_bfloat16 g_ao_hi[NTOK * C_]; // attn out [t][h*32+d]
__device__ __align__(16) __nv_bfloat16 g_ao_lo[NTOK * C_];

// ---------------- warp MMA helpers (HMMA via mma.sync, legal on sm_103) --------
__device__ __forceinline__ uint32_t smem_u32(const void* p) {
    uint32_t a;
    asm("{ .reg .u64 t; cvta.to.shared.u64 t, %1; cvt.u32.u64 %0, t; }" : "=r"(a) : "l"(p));
    return a;
}
__device__ __forceinline__ void ldsm_x4(uint32_t& r0, uint32_t& r1, uint32_t& r2, uint32_t& r3,
                                        uint32_t addr) {
    asm volatile("ldmatrix.sync.aligned.m8n8.x4.shared.b16 {%0,%1,%2,%3}, [%4];"
                 : "=r"(r0), "=r"(r1), "=r"(r2), "=r"(r3) : "r"(addr));
}
__device__ __forceinline__ void ldsm_x4_t(uint32_t& r0, uint32_t& r1, uint32_t& r2, uint32_t& r3,
                                          uint32_t addr) {
    asm volatile("ldmatrix.sync.aligned.m8n8.x4.trans.shared.b16 {%0,%1,%2,%3}, [%4];"
                 : "=r"(r0), "=r"(r1), "=r"(r2), "=r"(r3) : "r"(addr));
}
__device__ __forceinline__ void mma_bf16(float* c, const uint32_t* a, const uint32_t* b) {
    asm volatile("mma.sync.aligned.m16n8k16.row.col.f32.bf16.bf16.f32 "
                 "{%0,%1,%2,%3}, {%4,%5,%6,%7}, {%8,%9}, {%0,%1,%2,%3};"
                 : "+f"(c[0]), "+f"(c[1]), "+f"(c[2]), "+f"(c[3])
                 : "r"(a[0]), "r"(a[1]), "r"(a[2]), "r"(a[3]), "r"(b[0]), "r"(b[1]));
}

#define BK 32
#define AST 40   // padded smem row stride in bf16 (80B: conflict-free ldmatrix)

// ---------------- fast exp on FMA/ALU pipes -------------------------------------
__device__ __forceinline__ float fast_exp(float x) {
    x = fmaxf(x, -87.0f);
    float y = x * 1.44269504088896341f;
    float n = rintf(y);
    float f = y - n;
    float t = f * 0.6931471805599453f;
    float p = 1.0f + t * (1.0f + t * (0.5f + t * (0.16666667f + t * (0.041666668f + t * 0.008333334f))));
    int e = (int)n;
    float s = __int_as_float((e + 127) << 23);
    return p * s;
}

__device__ __forceinline__ void split_bf16(float v, __nv_bfloat16& hi, __nv_bfloat16& lo) {
    hi = __float2bfloat16_rn(v);
    lo = __float2bfloat16_rn(v - __bfloat162float(hi));
}
__device__ __forceinline__ uint32_t pk2(__nv_bfloat16 a, __nv_bfloat16 b) {
    __nv_bfloat162 t(a, b);
    return *reinterpret_cast<uint32_t*>(&t);
}

// ---------------- 0) weight conversion f32 -> bf16 hi/lo ------------------------
__global__ void convert_w_kernel(const float* __restrict__ in_w, const float* __restrict__ out_w) {
    int i = blockIdx.x * 256 + threadIdx.x;
    if (i < 3 * C_ * C_) {
        __nv_bfloat16 h, l;
        split_bf16(in_w[i], h, l);
        g_wqkv_hi[i] = h; g_wqkv_lo[i] = l;
    }
    if (i < C_ * C_) {
        __nv_bfloat16 h, l;
        split_bf16(out_w[i], h, l);
        g_wout_hi[i] = h; g_wout_lo[i] = l;
    }
}

// ---------------- 1) spatial mean pool -----------------------------------------
__global__ void pool_kernel(const float* __restrict__ x) {
    int bc = blockIdx.x;
    const float* p = x + (size_t)bc * (H_ * W_);
    float s = 0.f;
    for (int i = threadIdx.x; i < H_ * W_; i += 256) s += p[i];
    __shared__ float red[8];
    for (int o = 16; o; o >>= 1) s += __shfl_xor_sync(0xffffffffu, s, o);
    if ((threadIdx.x & 31) == 0) red[threadIdx.x >> 5] = s;
    __syncthreads();
    if (threadIdx.x < 8) {
        s = red[threadIdx.x];
        for (int o = 4; o; o >>= 1) s += __shfl_xor_sync(0xffu, s, o);
        if (threadIdx.x == 0) g_pooled[bc] = s * (1.0f / (H_ * W_));
    }
}

// ---------------- 2) SE gate MLP -----------------------------------------------
__global__ void se_kernel(const float* __restrict__ w1, const float* __restrict__ b1,
                          const float* __restrict__ w2, const float* __restrict__ b2) {
    __shared__ float h1s[B_ * CR_];
    int tid = threadIdx.x;
    {
        int b = tid >> 6, j = tid & 63;
        float s = b1[j];
        const float* pw = w1 + j * C_;
        const float* pp = g_pooled + b * C_;
        for (int c = 0; c < C_; c++) s += pp[c] * pw[c];
        h1s[tid] = fmaxf(s, 0.f);
    }
    __syncthreads();
    for (int i = tid; i < B_ * C_; i += 512) {
        int b = i >> 8, c = i & 255;
        float s = b2[c];
        const float* pw = w2 + c * CR_;
        const float* ph = h1s + b * CR_;
        for (int j = 0; j < CR_; j++) s += ph[j] * pw[j];
        g_ca[i] = 1.0f / (1.0f + expf(-s));
    }
}

// ---------------- 3) gather gated windows into bf16 hi/lo token matrix ---------
__global__ void gather_kernel(const float* __restrict__ x) {
    int hp = blockIdx.x;
    int cg = blockIdx.y;
    int b  = blockIdx.z;
    __shared__ float tile[32][65];
    int tid = threadIdx.x;
    int wp = tid & 63, ci = tid >> 6;
    const float* base = x + (((size_t)(b * C_ + cg * 32)) << 12) + hp * W_;
#pragma unroll
    for (int i = 0; i < 8; i++) {
        int c = ci + i * 4;
        tile[c][wp] = base[((size_t)c << 12) + wp];
    }
    __syncthreads();
    int j = tid & 31, pi = tid >> 5;
    int hw = hp >> 3, r = hp & 7;
    float cav = g_ca[b * C_ + cg * 32 + j];
#pragma unroll
    for (int i = 0; i < 8; i++) {
        int wpp = pi + i * 8;
        int ww = wpp >> 3, cc = wpp & 7;
        int l = (hw * 8 + ww) * 8 + b;
        int t = l * 64 + (r * 8 + cc);
        float v = tile[j][wpp] * cav;
        __nv_bfloat16 h, lo;
        split_bf16(v, h, lo);
        size_t idx = (size_t)t * C_ + cg * 32 + j;
        g_xw_hi[idx] = h;
        g_xw_lo[idx] = lo;
    }
}

// ---------------- shared mainloop: bf16x3 HMMA GEMM ----------------------------
struct GemmSmem {
    __nv_bfloat16 Ah[128][AST];
    __nv_bfloat16 Al[128][AST];
    __nv_bfloat16 Bh[64][AST];
    __nv_bfloat16 Bl[64][AST];
};

__device__ __forceinline__ void gemm_mainloop(GemmSmem& sm,
    const __nv_bfloat16* __restrict__ Ah, const __nv_bfloat16* __restrict__ Al,
    const __nv_bfloat16* __restrict__ Bh, const __nv_bfloat16* __restrict__ Bl,
    int m0, int n0, float acc[4][2][4]) {
    int tid = threadIdx.x;
    int lane = tid & 31, wid = tid >> 5;
    int wm = wid & 1, wn = wid >> 1;
    int lrow = lane & 15, lkq = lane >> 4;

    uint32_t sAh0 = smem_u32(&sm.Ah[0][0]);
    uint32_t sAl0 = smem_u32(&sm.Al[0][0]);
    uint32_t sBh0 = smem_u32(&sm.Bh[0][0]);
    uint32_t sBl0 = smem_u32(&sm.Bl[0][0]);

    for (int chunk = 0; chunk < 8; chunk++) {
        int k0 = chunk * BK;
#pragma unroll
        for (int p = 0; p < 2; p++) {
            int i = tid + p * 256;
            int row = i >> 2, q = i & 3;
            size_t gi = (size_t)(m0 + row) * C_ + k0 + q * 8;
            *(uint4*)&sm.Ah[row][q * 8] = *(const uint4*)(Ah + gi);
            *(uint4*)&sm.Al[row][q * 8] = *(const uint4*)(Al + gi);
        }
        {
            int row = tid >> 2, q = tid & 3;
            size_t gi = (size_t)(n0 + row) * C_ + k0 + q * 8;
            *(uint4*)&sm.Bh[row][q * 8] = *(const uint4*)(Bh + gi);
            *(uint4*)&sm.Bl[row][q * 8] = *(const uint4*)(Bl + gi);
        }
        __syncthreads();

#pragma unroll
        for (int ks = 0; ks < 2; ks++) {
            int kk = ks * 16 + lkq * 8;
            uint32_t ah[4][4], al[4][4], bh[4], bl[4];
#pragma unroll
            for (int mt = 0; mt < 4; mt++) {
                int row = wm * 64 + mt * 16 + lrow;
                uint32_t off = (uint32_t)(row * AST + kk) * 2;
                ldsm_x4(ah[mt][0], ah[mt][1], ah[mt][2], ah[mt][3], sAh0 + off);
                ldsm_x4(al[mt][0], al[mt][1], al[mt][2], al[mt][3], sAl0 + off);
            }
            {
                int row = wn * 16 + lrow;
                uint32_t off = (uint32_t)(row * AST + kk) * 2;
                ldsm_x4(bh[0], bh[1], bh[2], bh[3], sBh0 + off);
                ldsm_x4(bl[0], bl[1], bl[2], bl[3], sBl0 + off);
            }
            uint32_t b0h[2] = { bh[0], bh[2] }, b1h[2] = { bh[1], bh[3] };
            uint32_t b0l[2] = { bl[0], bl[2] }, b1l[2] = { bl[1], bl[3] };
#pragma unroll
            for (int mt = 0; mt < 4; mt++) {
                mma_bf16(acc[mt][0], ah[mt], b0h);
                mma_bf16(acc[mt][1], ah[mt], b1h);
                mma_bf16(acc[mt][0], ah[mt], b0l);
                mma_bf16(acc[mt][1], ah[mt], b1l);
                mma_bf16(acc[mt][0], al[mt], b0h);
                mma_bf16(acc[mt][1], al[mt], b1h);
            }
        }
        __syncthreads();
    }
}

// ---------------- 4) QKV projection (HMMA bf16x3) ------------------------------
__global__ __launch_bounds__(256) void qkv_mma_kernel(const float* __restrict__ bias) {
    __shared__ GemmSmem sm;
    int m0 = blockIdx.x * 128;
    int n0 = blockIdx.y * 64;
    float acc[4][2][4];
#pragma unroll
    for (int mt = 0; mt < 4; mt++)
#pragma unroll
        for (int nt = 0; nt < 2; nt++)
#pragma unroll
            for (int j = 0; j < 4; j++) acc[mt][nt][j] = 0.f;

    gemm_mainloop(sm, g_xw_hi, g_xw_lo, g_wqkv_hi, g_wqkv_lo, m0, n0, acc);

    int lane = threadIdx.x & 31, wid = threadIdx.x >> 5;
    int wm = wid & 1, wn = wid >> 1;
    int sec = n0 >> 8;                 // 0=Q, 1=K, 2=V
    __nv_bfloat16* dh = (sec == 0) ? g_qh : (sec == 1) ? g_kh : g_vh;
    __nv_bfloat16* dl = (sec == 0) ? g_ql : (sec == 1) ? g_kl : g_vl;
    float scale = (sec == 0) ? QK_SCALE : 1.0f;
    int l = (m0 >> 6) + wm;
    int r = lane >> 2;
#pragma unroll
    for (int mt = 0; mt < 4; mt++) {
#pragma unroll
        for (int nt = 0; nt < 2; nt++) {
            int col = n0 + wn * 16 + nt * 8 + (lane & 3) * 2;
            int oc = col & 255;
            int h = oc >> 5, d = oc & 31;
            float2 bi = *(const float2*)&bias[col];
#pragma unroll
            for (int half = 0; half < 2; half++) {
                int n = mt * 16 + r + half * 8;
                float v0 = (acc[mt][nt][half * 2 + 0] + bi.x) * scale;
                float v1 = (acc[mt][nt][half * 2 + 1] + bi.y) * scale;
                __nv_bfloat16 h0, l0, h1, l1;
                split_bf16(v0, h0, l0);
                split_bf16(v1, h1, l1);
                size_t idx = (((size_t)(n * NH_ + h) * L_ + l) << 5) + d;
                *(uint32_t*)(dh + idx) = pk2(h0, h1);
                *(uint32_t*)(dl + idx) = pk2(l0, l1);
            }
        }
    }
}

// ---------------- 5) attention (HMMA flash, bf16x3) ----------------------------
// block = 128 q rows of one (n,h); 8 warps x 16 rows. kt loop over 8 x 64 keys.
__global__ __launch_bounds__(256, 2) void attn_mma_kernel() {
    int qt = blockIdx.x;   // 0..3
    int h  = blockIdx.y;   // 0..7
    int n  = blockIdx.z;   // 0..63
    __shared__ __nv_bfloat16 Qh[128][AST], Ql[128][AST];
    __shared__ __nv_bfloat16 Kh[64][AST],  Kl[64][AST];
    __shared__ __nv_bfloat16 Vh[64][AST],  Vl[64][AST];

    size_t head = ((size_t)(n * NH_ + h)) * L_ * HD_;
    const __nv_bfloat16* qh = g_qh + head;
    const __nv_bfloat16* ql = g_ql + head;
    const __nv_bfloat16* kh = g_kh + head;
    const __nv_bfloat16* kl = g_kl + head;
    const __nv_bfloat16* vh = g_vh + head;
    const __nv_bfloat16* vl = g_vl + head;

    int tid = threadIdx.x;
    int lane = tid & 31, wid = tid >> 5;

    // load Q tile (128 rows x 32)
#pragma unroll
    for (int p = 0; p < 2; p++) {
        int i = tid + p * 256;
        int row = i >> 2, q = i & 3;
        size_t gi = (size_t)(qt * 128 + row) * HD_ + q * 8;
        *(uint4*)&Qh[row][q * 8] = *(const uint4*)(qh + gi);
        *(uint4*)&Ql[row][q * 8] = *(const uint4*)(ql + gi);
    }
    __syncthreads();

    uint32_t sQh = smem_u32(&Qh[0][0]), sQl = smem_u32(&Ql[0][0]);
    uint32_t sKh = smem_u32(&Kh[0][0]), sKl = smem_u32(&Kl[0][0]);
    uint32_t sVh = smem_u32(&Vh[0][0]), sVl = smem_u32(&Vl[0][0]);

    float o[4][4];
#pragma unroll
    for (int i = 0; i < 4; i++)
#pragma unroll
        for (int j = 0; j < 4; j++) o[i][j] = 0.f;
    float mrow[2] = { -1e30f, -1e30f };
    float lsum[2] = { 0.f, 0.f };

    int lrow = lane & 15, lkq = lane >> 4;

    for (int kt = 0; kt < 8; kt++) {
        {
            int row = tid >> 2, q = tid & 3;
            size_t gi = (size_t)(kt * 64 + row) * HD_ + q * 8;
            *(uint4*)&Kh[row][q * 8] = *(const uint4*)(kh + gi);
            *(uint4*)&Kl[row][q * 8] = *(const uint4*)(kl + gi);
            *(uint4*)&Vh[row][q * 8] = *(const uint4*)(vh + gi);
            *(uint4*)&Vl[row][q * 8] = *(const uint4*)(vl + gi);
        }
        __syncthreads();

        // ---- S = Q K^T (bf16x3) ----
        float s[8][4];
#pragma unroll
        for (int j = 0; j < 8; j++)
#pragma unroll
            for (int c = 0; c < 4; c++) s[j][c] = 0.f;

#pragma unroll
        for (int ks = 0; ks < 2; ks++) {
            int kk = ks * 16 + lkq * 8;
            uint32_t aqh[4], aql[4];
            uint32_t offq = (uint32_t)((wid * 16 + lrow) * AST + kk) * 2;
            ldsm_x4(aqh[0], aqh[1], aqh[2], aqh[3], sQh + offq);
            ldsm_x4(aql[0], aql[1], aql[2], aql[3], sQl + offq);
#pragma unroll
            for (int j = 0; j < 4; j++) {
                uint32_t bh4[4], bl4[4];
                uint32_t offk = (uint32_t)((j * 16 + lrow) * AST + kk) * 2;
                ldsm_x4(bh4[0], bh4[1], bh4[2], bh4[3], sKh + offk);
                ldsm_x4(bl4[0], bl4[1], bl4[2], bl4[3], sKl + offk);
                uint32_t b0h[2] = { bh4[0], bh4[2] }, b1h[2] = { bh4[1], bh4[3] };
                uint32_t b0l[2] = { bl4[0], bl4[2] }, b1l[2] = { bl4[1], bl4[3] };
                mma_bf16(s[2 * j + 0], aqh, b0h);
                mma_bf16(s[2 * j + 1], aqh, b1h);
                mma_bf16(s[2 * j + 0], aqh, b0l);
                mma_bf16(s[2 * j + 1], aqh, b1l);
                mma_bf16(s[2 * j + 0], aql, b0h);
                mma_bf16(s[2 * j + 1], aql, b1h);
            }
        }

        // ---- online softmax on fragments ----
        float mx0 = -1e30f, mx1 = -1e30f;
#pragma unroll
        for (int j = 0; j < 8; j++) {
            mx0 = fmaxf(mx0, fmaxf(s[j][0], s[j][1]));
            mx1 = fmaxf(mx1, fmaxf(s[j][2], s[j][3]));
        }
        mx0 = fmaxf(mx0, __shfl_xor_sync(0xffffffffu, mx0, 1));
        mx0 = fmaxf(mx0, __shfl_xor_sync(0xffffffffu, mx0, 2));
        mx1 = fmaxf(mx1, __shfl_xor_sync(0xffffffffu, mx1, 1));
        mx1 = fmaxf(mx1, __shfl_xor_sync(0xffffffffu, mx1, 2));
        float mn0 = fmaxf(mrow[0], mx0), mn1 = fmaxf(mrow[1], mx1);
        float al0 = fast_exp(mrow[0] - mn0), al1 = fast_exp(mrow[1] - mn1);
        float ps0 = 0.f, ps1 = 0.f;
#pragma unroll
        for (int j = 0; j < 8; j++) {
            s[j][0] = fast_exp(s[j][0] - mn0); ps0 += s[j][0];
            s[j][1] = fast_exp(s[j][1] - mn0); ps0 += s[j][1];
            s[j][2] = fast_exp(s[j][2] - mn1); ps1 += s[j][2];
            s[j][3] = fast_exp(s[j][3] - mn1); ps1 += s[j][3];
        }
        ps0 += __shfl_xor_sync(0xffffffffu, ps0, 1);
        ps0 += __shfl_xor_sync(0xffffffffu, ps0, 2);
        ps1 += __shfl_xor_sync(0xffffffffu, ps1, 1);
        ps1 += __shfl_xor_sync(0xffffffffu, ps1, 2);
        lsum[0] = lsum[0] * al0 + ps0;
        lsum[1] = lsum[1] * al1 + ps1;
        mrow[0] = mn0; mrow[1] = mn1;
#pragma unroll
        for (int nt = 0; nt < 4; nt++) {
            o[nt][0] *= al0; o[nt][1] *= al0;
            o[nt][2] *= al1; o[nt][3] *= al1;
        }

        // ---- O += P V (bf16x3, P from fragments) ----
#pragma unroll
        for (int ks = 0; ks < 4; ks++) {
            int j0 = 2 * ks, j1 = 2 * ks + 1;
            __nv_bfloat16 ph[8], pl[8];
#pragma unroll
            for (int c = 0; c < 4; c++) {
                split_bf16(s[j0][c], ph[c], pl[c]);
                split_bf16(s[j1][c], ph[4 + c], pl[4 + c]);
            }
            uint32_t aph[4] = { pk2(ph[0], ph[1]), pk2(ph[2], ph[3]),
                                pk2(ph[4], ph[5]), pk2(ph[6], ph[7]) };
            uint32_t apl[4] = { pk2(pl[0], pl[1]), pk2(pl[2], pl[3]),
                                pk2(pl[4], pl[5]), pk2(pl[6], pl[7]) };
#pragma unroll
            for (int half = 0; half < 2; half++) {
                uint32_t offv = (uint32_t)((ks * 16 + lrow) * AST + half * 16 + lkq * 8) * 2;
                uint32_t vh4[4], vl4[4];
                ldsm_x4_t(vh4[0], vh4[1], vh4[2], vh4[3], sVh + offv);
                ldsm_x4_t(vl4[0], vl4[1], vl4[2], vl4[3], sVl + offv);
                uint32_t bv0h[2] = { vh4[0], vh4[1] }, bv1h[2] = { vh4[2], vh4[3] };
                uint32_t bv0l[2] = { vl4[0], vl4[1] }, bv1l[2] = { vl4[2], vl4[3] };
                int nt0 = half * 2, nt1 = half * 2 + 1;
                mma_bf16(o[nt0], aph, bv0h);
                mma_bf16(o[nt1], aph, bv1h);
                mma_bf16(o[nt0], aph, bv0l);
                mma_bf16(o[nt1], aph, bv1l);
                mma_bf16(o[nt0], apl, bv0h);
                mma_bf16(o[nt1], apl, bv1h);
            }
        }
        __syncthreads();
    }

    // ---- epilogue: write ao hi/lo ----
    int r = lane >> 2, cp = (lane & 3) * 2;
#pragma unroll
    for (int half = 0; half < 2; half++) {
        int row = wid * 16 + r + half * 8;
        int l = qt * 128 + row;
        float inv = 1.0f / lsum[half];
        size_t base = ((size_t)(l * 64 + n)) * C_ + h * 32;
#pragma unroll
        for (int nt = 0; nt < 4; nt++) {
            float v0 = o[nt][half * 2 + 0] * inv;
            float v1 = o[nt][half * 2 + 1] * inv;
            __nv_bfloat16 h0, l0, h1, l1;
            split_bf16(v0, h0, l0);
            split_bf16(v1, h1, l1);
            size_t idx = base + nt * 8 + cp;
            *(uint32_t*)(g_ao_hi + idx) = pk2(h0, h1);
            *(uint32_t*)(g_ao_lo + idx) = pk2(l0, l1);
        }
    }
}

// ---------------- 6) out-proj (HMMA bf16x3) + gated residual -------------------
__global__ __launch_bounds__(256) void outproj_mma_kernel(const float* __restrict__ bias,
                                                          const float* __restrict__ x,
                                                          float* __restrict__ out) {
    __shared__ GemmSmem sm;
    int m0 = blockIdx.x * 128;
    int n0 = blockIdx.y * 64;
    float acc[4][2][4];
#pragma unroll
    for (int mt = 0; mt < 4; mt++)
#pragma unroll
        for (int nt = 0; nt < 2; nt++)
#pragma unroll
            for (int j = 0; j < 4; j++) acc[mt][nt][j] = 0.f;

    gemm_mainloop(sm, g_ao_hi, g_ao_lo, g_wout_hi, g_wout_lo, m0, n0, acc);

    int lane = threadIdx.x & 31, wid = threadIdx.x >> 5;
    int wm = wid & 1, wn = wid >> 1;
    int l = (m0 >> 6) + wm;
    int win = l >> 3, b = l & 7;
    int r = lane >> 2;
#pragma unroll
    for (int mt = 0; mt < 4; mt++) {
#pragma unroll
        for (int nt = 0; nt < 2; nt++) {
            int col = n0 + wn * 16 + nt * 8 + (lane & 3) * 2;
            float2 bi = *(const float2*)&bias[col];
            float ca0 = g_ca[b * C_ + col];
            float ca1 = g_ca[b * C_ + col + 1];
#pragma unroll
            for (int half = 0; half < 2; half++) {
                int wq = mt * 16 + r + half * 8;
                size_t idx0 = (((size_t)(b * C_ + col)) * H_ + win) * W_ + wq;
                size_t idx1 = idx0 + (size_t)H_ * W_;
                out[idx0] = x[idx0] * ca0 + acc[mt][nt][half * 2 + 0] + bi.x;
                out[idx1] = x[idx1] * ca1 + acc[mt][nt][half * 2 + 1] + bi.y;
            }
        }
    }
}

// ---------------- launch --------------------------------------------------------
extern "C" void kernel_launch(void* const* d_in, const int* in_sizes, int n_in,
                              void* d_out, int out_size) {
    const float* x     = (const float*)d_in[0];
    const float* ca_w1 = (const float*)d_in[1];
    const float* ca_b1 = (const float*)d_in[2];
    const float* ca_w2 = (const float*)d_in[3];
    const float* ca_b2 = (const float*)d_in[4];
    const float* in_w  = (const float*)d_in[5];
    const float* in_b  = (const float*)d_in[6];
    const float* out_w = (const float*)d_in[7];
    const float* out_b = (const float*)d_in[8];
    float* out = (float*)d_out;

    convert_w_kernel<<<(3 * C_ * C_ + 255) / 256, 256>>>(in_w, out_w);
    pool_kernel<<<B_ * C_, 256>>>(x);
    se_kernel<<<1, 512>>>(ca_w1, ca_b1, ca_w2, ca_b2);
    gather_kernel<<<dim3(64, 8, 8), 256>>>(x);
    qkv_mma_kernel<<<dim3(NTOK / 128, 12), 256>>>(in_b);
    attn_mma_kernel<<<dim3(4, 8, 64), 256>>>();
    outproj_mma_kernel<<<dim3(NTOK / 128, 4), 256>>>(out_b, x, out);
}

// round 6
// speedup vs baseline: 2.9264x; 1.5540x over previous
#include <cuda_runtime.h>
#include <cuda_fp16.h>
#include <cstdint>
#include <math.h>

// Problem constants
#define B_  8
#define C_  256
#define H_  64
#define W_  64
#define CR_ 64
#define L_  512
#define N_  64
#define NH_ 8
#define HD_ 32
#define NTOK (L_ * N_)          // 32768
#define QK_SCALE 0.17677669529663687f  // 1/sqrt(32)

// ---------------- scratch (device globals; no allocations allowed) -------------
__device__ float g_pooled[B_ * C_];
__device__ float g_ca[B_ * C_];
__device__ __align__(16) __half g_xw[NTOK * C_];      // gated tokens [t][c]
__device__ __align__(16) __half g_wqkv[3 * C_ * C_];
__device__ __align__(16) __half g_wout[C_ * C_];
// Q/K/V fp16, layout [n][h][l][d] (Q has scale folded)
__device__ __align__(16) __half g_q[N_ * NH_ * L_ * HD_];
__device__ __align__(16) __half g_k[N_ * NH_ * L_ * HD_];
__device__ __align__(16) __half g_v[N_ * NH_ * L_ * HD_];
__device__ __align__(16) __half g_ao[NTOK * C_];      // attn out [t][h*32+d]

// ---------------- warp MMA helpers (HMMA via mma.sync, legal on sm_103) --------
__device__ __forceinline__ uint32_t smem_u32(const void* p) {
    uint32_t a;
    asm("{ .reg .u64 t; cvta.to.shared.u64 t, %1; cvt.u32.u64 %0, t; }" : "=r"(a) : "l"(p));
    return a;
}
__device__ __forceinline__ void ldsm_x4(uint32_t& r0, uint32_t& r1, uint32_t& r2, uint32_t& r3,
                                        uint32_t addr) {
    asm volatile("ldmatrix.sync.aligned.m8n8.x4.shared.b16 {%0,%1,%2,%3}, [%4];"
                 : "=r"(r0), "=r"(r1), "=r"(r2), "=r"(r3) : "r"(addr));
}
__device__ __forceinline__ void ldsm_x4_t(uint32_t& r0, uint32_t& r1, uint32_t& r2, uint32_t& r3,
                                          uint32_t addr) {
    asm volatile("ldmatrix.sync.aligned.m8n8.x4.trans.shared.b16 {%0,%1,%2,%3}, [%4];"
                 : "=r"(r0), "=r"(r1), "=r"(r2), "=r"(r3) : "r"(addr));
}
__device__ __forceinline__ void mma_f16(float* c, const uint32_t* a, const uint32_t* b) {
    asm volatile("mma.sync.aligned.m16n8k16.row.col.f32.f16.f16.f32 "
                 "{%0,%1,%2,%3}, {%4,%5,%6,%7}, {%8,%9}, {%0,%1,%2,%3};"
                 : "+f"(c[0]), "+f"(c[1]), "+f"(c[2]), "+f"(c[3])
                 : "r"(a[0]), "r"(a[1]), "r"(a[2]), "r"(a[3]), "r"(b[0]), "r"(b[1]));
}

#define BK 32
#define AST 40   // padded smem row stride in halfs (80B: conflict-free ldmatrix)

// ---------------- fast exp on FMA/ALU pipes -------------------------------------
__device__ __forceinline__ float fast_exp(float x) {
    x = fmaxf(x, -87.0f);
    float y = x * 1.44269504088896341f;
    float n = rintf(y);
    float f = y - n;
    float t = f * 0.6931471805599453f;
    float p = 1.0f + t * (1.0f + t * (0.5f + t * (0.16666667f + t * (0.041666668f + t * 0.008333334f))));
    int e = (int)n;
    float s = __int_as_float((e + 127) << 23);
    return p * s;
}

__device__ __forceinline__ uint32_t pkh2(float a, float b) {
    __half2 t = __floats2half2_rn(a, b);
    return *reinterpret_cast<uint32_t*>(&t);
}

// ---------------- 0) weight conversion f32 -> fp16 ------------------------------
__global__ void convert_w_kernel(const float* __restrict__ in_w, const float* __restrict__ out_w) {
    int i = blockIdx.x * 256 + threadIdx.x;
    if (i < 3 * C_ * C_) g_wqkv[i] = __float2half_rn(in_w[i]);
    if (i < C_ * C_)     g_wout[i] = __float2half_rn(out_w[i]);
}

// ---------------- 1) spatial mean pool -----------------------------------------
__global__ void pool_kernel(const float* __restrict__ x) {
    int bc = blockIdx.x;
    const float* p = x + (size_t)bc * (H_ * W_);
    float s = 0.f;
    for (int i = threadIdx.x; i < H_ * W_; i += 256) s += p[i];
    __shared__ float red[8];
    for (int o = 16; o; o >>= 1) s += __shfl_xor_sync(0xffffffffu, s, o);
    if ((threadIdx.x & 31) == 0) red[threadIdx.x >> 5] = s;
    __syncthreads();
    if (threadIdx.x < 8) {
        s = red[threadIdx.x];
        for (int o = 4; o; o >>= 1) s += __shfl_xor_sync(0xffu, s, o);
        if (threadIdx.x == 0) g_pooled[bc] = s * (1.0f / (H_ * W_));
    }
}

// ---------------- 2) SE gate MLP -----------------------------------------------
__global__ void se_kernel(const float* __restrict__ w1, const float* __restrict__ b1,
                          const float* __restrict__ w2, const float* __restrict__ b2) {
    __shared__ float h1s[B_ * CR_];
    int tid = threadIdx.x;
    {
        int b = tid >> 6, j = tid & 63;
        float s = b1[j];
        const float* pw = w1 + j * C_;
        const float* pp = g_pooled + b * C_;
        for (int c = 0; c < C_; c++) s += pp[c] * pw[c];
        h1s[tid] = fmaxf(s, 0.f);
    }
    __syncthreads();
    for (int i = tid; i < B_ * C_; i += 512) {
        int b = i >> 8, c = i & 255;
        float s = b2[c];
        const float* pw = w2 + c * CR_;
        const float* ph = h1s + b * CR_;
        for (int j = 0; j < CR_; j++) s += ph[j] * pw[j];
        g_ca[i] = 1.0f / (1.0f + expf(-s));
    }
}

// ---------------- 3) gather gated windows into fp16 token matrix ---------------
__global__ void gather_kernel(const float* __restrict__ x) {
    int hp = blockIdx.x;
    int cg = blockIdx.y;
    int b  = blockIdx.z;
    __shared__ float tile[32][65];
    int tid = threadIdx.x;
    int wp = tid & 63, ci = tid >> 6;
    const float* base = x + (((size_t)(b * C_ + cg * 32)) << 12) + hp * W_;
#pragma unroll
    for (int i = 0; i < 8; i++) {
        int c = ci + i * 4;
        tile[c][wp] = base[((size_t)c << 12) + wp];
    }
    __syncthreads();
    int j = tid & 31, pi = tid >> 5;
    int hw = hp >> 3, r = hp & 7;
    float cav = g_ca[b * C_ + cg * 32 + j];
#pragma unroll
    for (int i = 0; i < 8; i++) {
        int wpp = pi + i * 8;
        int ww = wpp >> 3, cc = wpp & 7;
        int l = (hw * 8 + ww) * 8 + b;
        int t = l * 64 + (r * 8 + cc);
        g_xw[(size_t)t * C_ + cg * 32 + j] = __float2half_rn(tile[j][wpp] * cav);
    }
}

// ---------------- shared mainloop: fp16 HMMA GEMM (single pass) ----------------
struct GemmSmem {
    __half A[128][AST];
    __half Bm[64][AST];
};

__device__ __forceinline__ void gemm_mainloop(GemmSmem& sm,
    const __half* __restrict__ A, const __half* __restrict__ Bm,
    int m0, int n0, float acc[4][2][4]) {
    int tid = threadIdx.x;
    int lane = tid & 31, wid = tid >> 5;
    int wm = wid & 1, wn = wid >> 1;
    int lrow = lane & 15, lkq = lane >> 4;

    uint32_t sA0 = smem_u32(&sm.A[0][0]);
    uint32_t sB0 = smem_u32(&sm.Bm[0][0]);

    for (int chunk = 0; chunk < 8; chunk++) {
        int k0 = chunk * BK;
#pragma unroll
        for (int p = 0; p < 2; p++) {
            int i = tid + p * 256;
            int row = i >> 2, q = i & 3;
            *(uint4*)&sm.A[row][q * 8] = *(const uint4*)(A + (size_t)(m0 + row) * C_ + k0 + q * 8);
        }
        {
            int row = tid >> 2, q = tid & 3;
            *(uint4*)&sm.Bm[row][q * 8] = *(const uint4*)(Bm + (size_t)(n0 + row) * C_ + k0 + q * 8);
        }
        __syncthreads();

#pragma unroll
        for (int ks = 0; ks < 2; ks++) {
            int kk = ks * 16 + lkq * 8;
            uint32_t a4[4][4], b4[4];
#pragma unroll
            for (int mt = 0; mt < 4; mt++) {
                int row = wm * 64 + mt * 16 + lrow;
                ldsm_x4(a4[mt][0], a4[mt][1], a4[mt][2], a4[mt][3],
                        sA0 + (uint32_t)(row * AST + kk) * 2);
            }
            {
                int row = wn * 16 + lrow;
                ldsm_x4(b4[0], b4[1], b4[2], b4[3], sB0 + (uint32_t)(row * AST + kk) * 2);
            }
            uint32_t b0[2] = { b4[0], b4[2] }, b1[2] = { b4[1], b4[3] };
#pragma unroll
            for (int mt = 0; mt < 4; mt++) {
                mma_f16(acc[mt][0], a4[mt], b0);
                mma_f16(acc[mt][1], a4[mt], b1);
            }
        }
        __syncthreads();
    }
}

// ---------------- 4) QKV projection (fp16 HMMA) --------------------------------
__global__ __launch_bounds__(256) void qkv_mma_kernel(const float* __restrict__ bias) {
    __shared__ GemmSmem sm;
    int m0 = blockIdx.x * 128;
    int n0 = blockIdx.y * 64;
    float acc[4][2][4];
#pragma unroll
    for (int mt = 0; mt < 4; mt++)
#pragma unroll
        for (int nt = 0; nt < 2; nt++)
#pragma unroll
            for (int j = 0; j < 4; j++) acc[mt][nt][j] = 0.f;

    gemm_mainloop(sm, g_xw, g_wqkv, m0, n0, acc);

    int lane = threadIdx.x & 31, wid = threadIdx.x >> 5;
    int wm = wid & 1, wn = wid >> 1;
    int sec = n0 >> 8;                 // 0=Q, 1=K, 2=V
    __half* dst = (sec == 0) ? g_q : (sec == 1) ? g_k : g_v;
    float scale = (sec == 0) ? QK_SCALE : 1.0f;
    int l = (m0 >> 6) + wm;
    int r = lane >> 2;
#pragma unroll
    for (int mt = 0; mt < 4; mt++) {
#pragma unroll
        for (int nt = 0; nt < 2; nt++) {
            int col = n0 + wn * 16 + nt * 8 + (lane & 3) * 2;
            int oc = col & 255;
            int h = oc >> 5, d = oc & 31;
            float2 bi = *(const float2*)&bias[col];
#pragma unroll
            for (int half = 0; half < 2; half++) {
                int n = mt * 16 + r + half * 8;
                float v0 = (acc[mt][nt][half * 2 + 0] + bi.x) * scale;
                float v1 = (acc[mt][nt][half * 2 + 1] + bi.y) * scale;
                size_t idx = (((size_t)(n * NH_ + h) * L_ + l) << 5) + d;
                *(uint32_t*)(dst + idx) = pkh2(v0, v1);
            }
        }
    }
}

// ---------------- 5) attention (fp16 HMMA flash) -------------------------------
// block = 128 q rows of one (n,h); 8 warps x 16 rows. kt loop over 8 x 64 keys.
__global__ __launch_bounds__(256, 2) void attn_mma_kernel() {
    int qt = blockIdx.x;   // 0..3
    int h  = blockIdx.y;   // 0..7
    int n  = blockIdx.z;   // 0..63
    __shared__ __half Qs[128][AST];
    __shared__ __half Ks[64][AST];
    __shared__ __half Vs[64][AST];

    size_t head = ((size_t)(n * NH_ + h)) * L_ * HD_;
    const __half* qg = g_q + head;
    const __half* kg = g_k + head;
    const __half* vg = g_v + head;

    int tid = threadIdx.x;
    int lane = tid & 31, wid = tid >> 5;

    // load Q tile (128 rows x 32)
#pragma unroll
    for (int p = 0; p < 2; p++) {
        int i = tid + p * 256;
        int row = i >> 2, q = i & 3;
        *(uint4*)&Qs[row][q * 8] = *(const uint4*)(qg + (size_t)(qt * 128 + row) * HD_ + q * 8);
    }
    __syncthreads();

    uint32_t sQ = smem_u32(&Qs[0][0]);
    uint32_t sK = smem_u32(&Ks[0][0]);
    uint32_t sV = smem_u32(&Vs[0][0]);

    float o[4][4];
#pragma unroll
    for (int i = 0; i < 4; i++)
#pragma unroll
        for (int j = 0; j < 4; j++) o[i][j] = 0.f;
    float mrow[2] = { -1e30f, -1e30f };
    float lsum[2] = { 0.f, 0.f };

    int lrow = lane & 15, lkq = lane >> 4;

    for (int kt = 0; kt < 8; kt++) {
        {
            int row = tid >> 2, q = tid & 3;
            size_t gi = (size_t)(kt * 64 + row) * HD_ + q * 8;
            *(uint4*)&Ks[row][q * 8] = *(const uint4*)(kg + gi);
            *(uint4*)&Vs[row][q * 8] = *(const uint4*)(vg + gi);
        }
        __syncthreads();

        // ---- S = Q K^T ----
        float s[8][4];
#pragma unroll
        for (int j = 0; j < 8; j++)
#pragma unroll
            for (int c = 0; c < 4; c++) s[j][c] = 0.f;

#pragma unroll
        for (int ks = 0; ks < 2; ks++) {
            int kk = ks * 16 + lkq * 8;
            uint32_t aq[4];
            ldsm_x4(aq[0], aq[1], aq[2], aq[3],
                    sQ + (uint32_t)((wid * 16 + lrow) * AST + kk) * 2);
#pragma unroll
            for (int j = 0; j < 4; j++) {
                uint32_t b4[4];
                ldsm_x4(b4[0], b4[1], b4[2], b4[3],
                        sK + (uint32_t)((j * 16 + lrow) * AST + kk) * 2);
                uint32_t b0[2] = { b4[0], b4[2] }, b1[2] = { b4[1], b4[3] };
                mma_f16(s[2 * j + 0], aq, b0);
                mma_f16(s[2 * j + 1], aq, b1);
            }
        }

        // ---- online softmax on fragments ----
        float mx0 = -1e30f, mx1 = -1e30f;
#pragma unroll
        for (int j = 0; j < 8; j++) {
            mx0 = fmaxf(mx0, fmaxf(s[j][0], s[j][1]));
            mx1 = fmaxf(mx1, fmaxf(s[j][2], s[j][3]));
        }
        mx0 = fmaxf(mx0, __shfl_xor_sync(0xffffffffu, mx0, 1));
        mx0 = fmaxf(mx0, __shfl_xor_sync(0xffffffffu, mx0, 2));
        mx1 = fmaxf(mx1, __shfl_xor_sync(0xffffffffu, mx1, 1));
        mx1 = fmaxf(mx1, __shfl_xor_sync(0xffffffffu, mx1, 2));
        float mn0 = fmaxf(mrow[0], mx0), mn1 = fmaxf(mrow[1], mx1);
        float al0 = fast_exp(mrow[0] - mn0), al1 = fast_exp(mrow[1] - mn1);
        float ps0 = 0.f, ps1 = 0.f;
#pragma unroll
        for (int j = 0; j < 8; j++) {
            s[j][0] = fast_exp(s[j][0] - mn0); ps0 += s[j][0];
            s[j][1] = fast_exp(s[j][1] - mn0); ps0 += s[j][1];
            s[j][2] = fast_exp(s[j][2] - mn1); ps1 += s[j][2];
            s[j][3] = fast_exp(s[j][3] - mn1); ps1 += s[j][3];
        }
        ps0 += __shfl_xor_sync(0xffffffffu, ps0, 1);
        ps0 += __shfl_xor_sync(0xffffffffu, ps0, 2);
        ps1 += __shfl_xor_sync(0xffffffffu, ps1, 1);
        ps1 += __shfl_xor_sync(0xffffffffu, ps1, 2);
        lsum[0] = lsum[0] * al0 + ps0;
        lsum[1] = lsum[1] * al1 + ps1;
        mrow[0] = mn0; mrow[1] = mn1;
#pragma unroll
        for (int nt = 0; nt < 4; nt++) {
            o[nt][0] *= al0; o[nt][1] *= al0;
            o[nt][2] *= al1; o[nt][3] *= al1;
        }

        // ---- O += P V (P from fragments, fp16) ----
#pragma unroll
        for (int ks = 0; ks < 4; ks++) {
            int j0 = 2 * ks, j1 = 2 * ks + 1;
            uint32_t ap[4] = { pkh2(s[j0][0], s[j0][1]), pkh2(s[j0][2], s[j0][3]),
                               pkh2(s[j1][0], s[j1][1]), pkh2(s[j1][2], s[j1][3]) };
#pragma unroll
            for (int half = 0; half < 2; half++) {
                uint32_t v4[4];
                ldsm_x4_t(v4[0], v4[1], v4[2], v4[3],
                          sV + (uint32_t)((ks * 16 + lrow) * AST + half * 16 + lkq * 8) * 2);
                uint32_t bv0[2] = { v4[0], v4[1] }, bv1[2] = { v4[2], v4[3] };
                mma_f16(o[half * 2 + 0], ap, bv0);
                mma_f16(o[half * 2 + 1], ap, bv1);
            }
        }
        __syncthreads();
    }

    // ---- epilogue: write ao ----
    int r = lane >> 2, cp = (lane & 3) * 2;
#pragma unroll
    for (int half = 0; half < 2; half++) {
        int row = wid * 16 + r + half * 8;
        int l = qt * 128 + row;
        float inv = 1.0f / lsum[half];
        size_t base = ((size_t)(l * 64 + n)) * C_ + h * 32;
#pragma unroll
        for (int nt = 0; nt < 4; nt++) {
            float v0 = o[nt][half * 2 + 0] * inv;
            float v1 = o[nt][half * 2 + 1] * inv;
            *(uint32_t*)(g_ao + base + nt * 8 + cp) = pkh2(v0, v1);
        }
    }
}

// ---------------- 6) out-proj (fp16 HMMA) + gated residual ---------------------
__global__ __launch_bounds__(256) void outproj_mma_kernel(const float* __restrict__ bias,
                                                          const float* __restrict__ x,
                                                          float* __restrict__ out) {
    __shared__ GemmSmem sm;
    int m0 = blockIdx.x * 128;
    int n0 = blockIdx.y * 64;
    float acc[4][2][4];
#pragma unroll
    for (int mt = 0; mt < 4; mt++)
#pragma unroll
        for (int nt = 0; nt < 2; nt++)
#pragma unroll
            for (int j = 0; j < 4; j++) acc[mt][nt][j] = 0.f;

    gemm_mainloop(sm, g_ao, g_wout, m0, n0, acc);

    int lane = threadIdx.x & 31, wid = threadIdx.x >> 5;
    int wm = wid & 1, wn = wid >> 1;
    int l = (m0 >> 6) + wm;
    int win = l >> 3, b = l & 7;
    int r = lane >> 2;
#pragma unroll
    for (int mt = 0; mt < 4; mt++) {
#pragma unroll
        for (int nt = 0; nt < 2; nt++) {
            int col = n0 + wn * 16 + nt * 8 + (lane & 3) * 2;
            float2 bi = *(const float2*)&bias[col];
            float ca0 = g_ca[b * C_ + col];
            float ca1 = g_ca[b * C_ + col + 1];
#pragma unroll
            for (int half = 0; half < 2; half++) {
                int wq = mt * 16 + r + half * 8;
                size_t idx0 = (((size_t)(b * C_ + col)) * H_ + win) * W_ + wq;
                size_t idx1 = idx0 + (size_t)H_ * W_;
                out[idx0] = x[idx0] * ca0 + acc[mt][nt][half * 2 + 0] + bi.x;
                out[idx1] = x[idx1] * ca1 + acc[mt][nt][half * 2 + 1] + bi.y;
            }
        }
    }
}

// ---------------- launch --------------------------------------------------------
extern "C" void kernel_launch(void* const* d_in, const int* in_sizes, int n_in,
                              void* d_out, int out_size) {
    const float* x     = (const float*)d_in[0];
    const float* ca_w1 = (const float*)d_in[1];
    const float* ca_b1 = (const float*)d_in[2];
    const float* ca_w2 = (const float*)d_in[3];
    const float* ca_b2 = (const float*)d_in[4];
    const float* in_w  = (const float*)d_in[5];
    const float* in_b  = (const float*)d_in[6];
    const float* out_w = (const float*)d_in[7];
    const float* out_b = (const float*)d_in[8];
    float* out = (float*)d_out;

    convert_w_kernel<<<(3 * C_ * C_ + 255) / 256, 256>>>(in_w, out_w);
    pool_kernel<<<B_ * C_, 256>>>(x);
    se_kernel<<<1, 512>>>(ca_w1, ca_b1, ca_w2, ca_b2);
    gather_kernel<<<dim3(64, 8, 8), 256>>>(x);
    qkv_mma_kernel<<<dim3(NTOK / 128, 12), 256>>>(in_b);
    attn_mma_kernel<<<dim3(4, 8, 64), 256>>>();
    outproj_mma_kernel<<<dim3(NTOK / 128, 4), 256>>>(out_b, x, out);
}

// round 7
// speedup vs baseline: 3.1771x; 1.0857x over previous
#include <cuda_runtime.h>
#include <cuda_fp16.h>
#include <cstdint>
#include <math.h>

// Problem constants
#define B_  8
#define C_  256
#define H_  64
#define W_  64
#define CR_ 64
#define L_  512
#define N_  64
#define NH_ 8
#define HD_ 32
#define NTOK (L_ * N_)          // 32768
#define QK_SCALE 0.17677669529663687f  // 1/sqrt(32)

// ---------------- scratch (device globals; no allocations allowed) -------------
__device__ float g_pooled[B_ * C_];
__device__ float g_ca[B_ * C_];
__device__ __align__(16) __half g_xw[NTOK * C_];      // gated tokens [t][c]
__device__ __align__(16) __half g_wqkv[3 * C_ * C_];
__device__ __align__(16) __half g_wout[C_ * C_];
// Q/K/V fp16, layout [n][h][l][d] (Q has scale folded)
__device__ __align__(16) __half g_q[N_ * NH_ * L_ * HD_];
__device__ __align__(16) __half g_k[N_ * NH_ * L_ * HD_];
__device__ __align__(16) __half g_v[N_ * NH_ * L_ * HD_];
__device__ __align__(16) __half g_ao[NTOK * C_];      // attn out [t][h*32+d]

// ---------------- PTX helpers ---------------------------------------------------
__device__ __forceinline__ uint32_t smem_u32(const void* p) {
    uint32_t a;
    asm("{ .reg .u64 t; cvta.to.shared.u64 t, %1; cvt.u32.u64 %0, t; }" : "=r"(a) : "l"(p));
    return a;
}
__device__ __forceinline__ void ldsm_x4(uint32_t& r0, uint32_t& r1, uint32_t& r2, uint32_t& r3,
                                        uint32_t addr) {
    asm volatile("ldmatrix.sync.aligned.m8n8.x4.shared.b16 {%0,%1,%2,%3}, [%4];"
                 : "=r"(r0), "=r"(r1), "=r"(r2), "=r"(r3) : "r"(addr));
}
__device__ __forceinline__ void ldsm_x4_t(uint32_t& r0, uint32_t& r1, uint32_t& r2, uint32_t& r3,
                                          uint32_t addr) {
    asm volatile("ldmatrix.sync.aligned.m8n8.x4.trans.shared.b16 {%0,%1,%2,%3}, [%4];"
                 : "=r"(r0), "=r"(r1), "=r"(r2), "=r"(r3) : "r"(addr));
}
__device__ __forceinline__ void mma_f16(float* c, const uint32_t* a, const uint32_t* b) {
    asm volatile("mma.sync.aligned.m16n8k16.row.col.f32.f16.f16.f32 "
                 "{%0,%1,%2,%3}, {%4,%5,%6,%7}, {%8,%9}, {%0,%1,%2,%3};"
                 : "+f"(c[0]), "+f"(c[1]), "+f"(c[2]), "+f"(c[3])
                 : "r"(a[0]), "r"(a[1]), "r"(a[2]), "r"(a[3]), "r"(b[0]), "r"(b[1]));
}
__device__ __forceinline__ void cp16(uint32_t saddr, const void* g) {
    asm volatile("cp.async.cg.shared.global [%0], [%1], 16;" :: "r"(saddr), "l"(g));
}
#define CP_COMMIT() asm volatile("cp.async.commit_group;" ::: "memory")
#define CP_WAIT0()  asm volatile("cp.async.wait_group 0;" ::: "memory")

#define BK 32
#define AST 40   // padded smem row stride in halfs (80B: conflict-free ldmatrix)

// ---------------- fast exp on FMA/ALU pipes -------------------------------------
__device__ __forceinline__ float fast_exp(float x) {
    x = fmaxf(x, -87.0f);
    float y = x * 1.44269504088896341f;
    float n = rintf(y);
    float f = y - n;
    float t = f * 0.6931471805599453f;
    float p = 1.0f + t * (1.0f + t * (0.5f + t * (0.16666667f + t * (0.041666668f + t * 0.008333334f))));
    int e = (int)n;
    float s = __int_as_float((e + 127) << 23);
    return p * s;
}
__device__ __forceinline__ uint32_t pkh2(float a, float b) {
    __half2 t = __floats2half2_rn(a, b);
    return *reinterpret_cast<uint32_t*>(&t);
}

// ---------------- 1) merged prep: pool (blocks 0..2047) + W convert -------------
__global__ void prep_kernel(const float* __restrict__ x,
                            const float* __restrict__ in_w, const float* __restrict__ out_w) {
    int bid = blockIdx.x;
    if (bid < B_ * C_) {
        const float* p = x + (size_t)bid * (H_ * W_);
        float s = 0.f;
        for (int i = threadIdx.x; i < H_ * W_; i += 256) s += p[i];
        __shared__ float red[8];
        for (int o = 16; o; o >>= 1) s += __shfl_xor_sync(0xffffffffu, s, o);
        if ((threadIdx.x & 31) == 0) red[threadIdx.x >> 5] = s;
        __syncthreads();
        if (threadIdx.x < 8) {
            s = red[threadIdx.x];
            for (int o = 4; o; o >>= 1) s += __shfl_xor_sync(0xffu, s, o);
            if (threadIdx.x == 0) g_pooled[bid] = s * (1.0f / (H_ * W_));
        }
    } else {
        int i = (bid - B_ * C_) * 256 + threadIdx.x;
        if (i < 3 * C_ * C_) g_wqkv[i] = __float2half_rn(in_w[i]);
        if (i < C_ * C_)     g_wout[i] = __float2half_rn(out_w[i]);
    }
}

// ---------------- 2) SE gate MLP -----------------------------------------------
__global__ void se_kernel(const float* __restrict__ w1, const float* __restrict__ b1,
                          const float* __restrict__ w2, const float* __restrict__ b2) {
    __shared__ float h1s[B_ * CR_];
    int tid = threadIdx.x;
    {
        int b = tid >> 6, j = tid & 63;
        float s = b1[j];
        const float* pw = w1 + j * C_;
        const float* pp = g_pooled + b * C_;
        for (int c = 0; c < C_; c++) s += pp[c] * pw[c];
        h1s[tid] = fmaxf(s, 0.f);
    }
    __syncthreads();
    for (int i = tid; i < B_ * C_; i += 512) {
        int b = i >> 8, c = i & 255;
        float s = b2[c];
        const float* pw = w2 + c * CR_;
        const float* ph = h1s + b * CR_;
        for (int j = 0; j < CR_; j++) s += ph[j] * pw[j];
        g_ca[i] = 1.0f / (1.0f + expf(-s));
    }
}

// ---------------- 3) gather gated windows into fp16 token matrix ---------------
__global__ void gather_kernel(const float* __restrict__ x) {
    int hp = blockIdx.x;
    int cg = blockIdx.y;
    int b  = blockIdx.z;
    __shared__ float tile[32][65];
    int tid = threadIdx.x;
    int wp = tid & 63, ci = tid >> 6;
    const float* base = x + (((size_t)(b * C_ + cg * 32)) << 12) + hp * W_;
#pragma unroll
    for (int i = 0; i < 8; i++) {
        int c = ci + i * 4;
        tile[c][wp] = base[((size_t)c << 12) + wp];
    }
    __syncthreads();
    int j = tid & 31, pi = tid >> 5;
    int hw = hp >> 3, r = hp & 7;
    float cav = g_ca[b * C_ + cg * 32 + j];
#pragma unroll
    for (int i = 0; i < 8; i++) {
        int wpp = pi + i * 8;
        int ww = wpp >> 3, cc = wpp & 7;
        int l = (hw * 8 + ww) * 8 + b;
        int t = l * 64 + (r * 8 + cc);
        g_xw[(size_t)t * C_ + cg * 32 + j] = __float2half_rn(tile[j][wpp] * cav);
    }
}

// ---------------- shared mainloop: fp16 HMMA GEMM, cp.async double-buffered ----
struct GemmSmem {
    __half A[2][128][AST];
    __half Bm[2][64][AST];
};

__device__ __forceinline__ void gemm_load_chunk(GemmSmem& sm, int buf,
    const __half* __restrict__ A, const __half* __restrict__ Bm,
    int m0, int n0, int k0, int tid) {
#pragma unroll
    for (int p = 0; p < 2; p++) {
        int i = tid + p * 256;
        int row = i >> 2, q = i & 3;
        cp16(smem_u32(&sm.A[buf][row][q * 8]), A + (size_t)(m0 + row) * C_ + k0 + q * 8);
    }
    {
        int row = tid >> 2, q = tid & 3;
        cp16(smem_u32(&sm.Bm[buf][row][q * 8]), Bm + (size_t)(n0 + row) * C_ + k0 + q * 8);
    }
    CP_COMMIT();
}

__device__ __forceinline__ void gemm_mainloop(GemmSmem& sm,
    const __half* __restrict__ A, const __half* __restrict__ Bm,
    int m0, int n0, float acc[4][2][4]) {
    int tid = threadIdx.x;
    int lane = tid & 31, wid = tid >> 5;
    int wm = wid & 1, wn = wid >> 1;
    int lrow = lane & 15, lkq = lane >> 4;

    gemm_load_chunk(sm, 0, A, Bm, m0, n0, 0, tid);

    for (int chunk = 0; chunk < 8; chunk++) {
        int buf = chunk & 1;
        CP_WAIT0();
        __syncthreads();
        if (chunk < 7)
            gemm_load_chunk(sm, buf ^ 1, A, Bm, m0, n0, (chunk + 1) * BK, tid);

        uint32_t sA0 = smem_u32(&sm.A[buf][0][0]);
        uint32_t sB0 = smem_u32(&sm.Bm[buf][0][0]);
#pragma unroll
        for (int ks = 0; ks < 2; ks++) {
            int kk = ks * 16 + lkq * 8;
            uint32_t a4[4][4], b4[4];
#pragma unroll
            for (int mt = 0; mt < 4; mt++) {
                int row = wm * 64 + mt * 16 + lrow;
                ldsm_x4(a4[mt][0], a4[mt][1], a4[mt][2], a4[mt][3],
                        sA0 + (uint32_t)(row * AST + kk) * 2);
            }
            {
                int row = wn * 16 + lrow;
                ldsm_x4(b4[0], b4[1], b4[2], b4[3], sB0 + (uint32_t)(row * AST + kk) * 2);
            }
            uint32_t b0[2] = { b4[0], b4[2] }, b1[2] = { b4[1], b4[3] };
#pragma unroll
            for (int mt = 0; mt < 4; mt++) {
                mma_f16(acc[mt][0], a4[mt], b0);
                mma_f16(acc[mt][1], a4[mt], b1);
            }
        }
    }
}

// ---------------- 4) QKV projection (fp16 HMMA) --------------------------------
__global__ __launch_bounds__(256, 2) void qkv_mma_kernel(const float* __restrict__ bias) {
    __shared__ GemmSmem sm;
    int m0 = blockIdx.x * 128;
    int n0 = blockIdx.y * 64;
    float acc[4][2][4];
#pragma unroll
    for (int mt = 0; mt < 4; mt++)
#pragma unroll
        for (int nt = 0; nt < 2; nt++)
#pragma unroll
            for (int j = 0; j < 4; j++) acc[mt][nt][j] = 0.f;

    gemm_mainloop(sm, g_xw, g_wqkv, m0, n0, acc);

    int lane = threadIdx.x & 31, wid = threadIdx.x >> 5;
    int wm = wid & 1, wn = wid >> 1;
    int sec = n0 >> 8;                 // 0=Q, 1=K, 2=V
    __half* dst = (sec == 0) ? g_q : (sec == 1) ? g_k : g_v;
    float scale = (sec == 0) ? QK_SCALE : 1.0f;
    int l = (m0 >> 6) + wm;
    int r = lane >> 2;
#pragma unroll
    for (int mt = 0; mt < 4; mt++) {
#pragma unroll
        for (int nt = 0; nt < 2; nt++) {
            int col = n0 + wn * 16 + nt * 8 + (lane & 3) * 2;
            int oc = col & 255;
            int h = oc >> 5, d = oc & 31;
            float2 bi = *(const float2*)&bias[col];
#pragma unroll
            for (int half = 0; half < 2; half++) {
                int n = mt * 16 + r + half * 8;
                float v0 = (acc[mt][nt][half * 2 + 0] + bi.x) * scale;
                float v1 = (acc[mt][nt][half * 2 + 1] + bi.y) * scale;
                size_t idx = (((size_t)(n * NH_ + h) * L_ + l) << 5) + d;
                *(uint32_t*)(dst + idx) = pkh2(v0, v1);
            }
        }
    }
}

// ---------------- 5) attention (fp16 HMMA flash, cp.async K/V pipeline) --------
__global__ __launch_bounds__(256, 2) void attn_mma_kernel() {
    int qt = blockIdx.x;   // 0..3
    int h  = blockIdx.y;   // 0..7
    int n  = blockIdx.z;   // 0..63
    __shared__ __half Qs[128][AST];
    __shared__ __half Ks[2][64][AST];
    __shared__ __half Vs[2][64][AST];

    size_t head = ((size_t)(n * NH_ + h)) * L_ * HD_;
    const __half* qg = g_q + head;
    const __half* kg = g_k + head;
    const __half* vg = g_v + head;

    int tid = threadIdx.x;
    int lane = tid & 31, wid = tid >> 5;
    int kvrow = tid >> 2, kvq = tid & 3;

    // issue K/V stage 0
    {
        size_t gi = (size_t)kvrow * HD_ + kvq * 8;
        cp16(smem_u32(&Ks[0][kvrow][kvq * 8]), kg + gi);
        cp16(smem_u32(&Vs[0][kvrow][kvq * 8]), vg + gi);
        CP_COMMIT();
    }
    // load Q tile (128 rows x 32) with plain loads (overlaps with cp.async)
#pragma unroll
    for (int p = 0; p < 2; p++) {
        int i = tid + p * 256;
        int row = i >> 2, q = i & 3;
        *(uint4*)&Qs[row][q * 8] = *(const uint4*)(qg + (size_t)(qt * 128 + row) * HD_ + q * 8);
    }

    uint32_t sQ = smem_u32(&Qs[0][0]);

    float o[4][4];
#pragma unroll
    for (int i = 0; i < 4; i++)
#pragma unroll
        for (int j = 0; j < 4; j++) o[i][j] = 0.f;
    float mrow[2] = { -1e30f, -1e30f };
    float lsum[2] = { 0.f, 0.f };

    int lrow = lane & 15, lkq = lane >> 4;

    for (int kt = 0; kt < 8; kt++) {
        int buf = kt & 1;
        CP_WAIT0();
        __syncthreads();
        if (kt < 7) {
            size_t gi = (size_t)((kt + 1) * 64 + kvrow) * HD_ + kvq * 8;
            cp16(smem_u32(&Ks[buf ^ 1][kvrow][kvq * 8]), kg + gi);
            cp16(smem_u32(&Vs[buf ^ 1][kvrow][kvq * 8]), vg + gi);
            CP_COMMIT();
        }
        uint32_t sK = smem_u32(&Ks[buf][0][0]);
        uint32_t sV = smem_u32(&Vs[buf][0][0]);

        // ---- S = Q K^T ----
        float s[8][4];
#pragma unroll
        for (int j = 0; j < 8; j++)
#pragma unroll
            for (int c = 0; c < 4; c++) s[j][c] = 0.f;

#pragma unroll
        for (int ks = 0; ks < 2; ks++) {
            int kk = ks * 16 + lkq * 8;
            uint32_t aq[4];
            ldsm_x4(aq[0], aq[1], aq[2], aq[3],
                    sQ + (uint32_t)((wid * 16 + lrow) * AST + kk) * 2);
#pragma unroll
            for (int j = 0; j < 4; j++) {
                uint32_t b4[4];
                ldsm_x4(b4[0], b4[1], b4[2], b4[3],
                        sK + (uint32_t)((j * 16 + lrow) * AST + kk) * 2);
                uint32_t b0[2] = { b4[0], b4[2] }, b1[2] = { b4[1], b4[3] };
                mma_f16(s[2 * j + 0], aq, b0);
                mma_f16(s[2 * j + 1], aq, b1);
            }
        }

        // ---- online softmax on fragments ----
        float mx0 = -1e30f, mx1 = -1e30f;
#pragma unroll
        for (int j = 0; j < 8; j++) {
            mx0 = fmaxf(mx0, fmaxf(s[j][0], s[j][1]));
            mx1 = fmaxf(mx1, fmaxf(s[j][2], s[j][3]));
        }
        mx0 = fmaxf(mx0, __shfl_xor_sync(0xffffffffu, mx0, 1));
        mx0 = fmaxf(mx0, __shfl_xor_sync(0xffffffffu, mx0, 2));
        mx1 = fmaxf(mx1, __shfl_xor_sync(0xffffffffu, mx1, 1));
        mx1 = fmaxf(mx1, __shfl_xor_sync(0xffffffffu, mx1, 2));
        float mn0 = fmaxf(mrow[0], mx0), mn1 = fmaxf(mrow[1], mx1);
        float al0 = fast_exp(mrow[0] - mn0), al1 = fast_exp(mrow[1] - mn1);
        float ps0 = 0.f, ps1 = 0.f;
#pragma unroll
        for (int j = 0; j < 8; j++) {
            s[j][0] = fast_exp(s[j][0] - mn0); ps0 += s[j][0];
            s[j][1] = fast_exp(s[j][1] - mn0); ps0 += s[j][1];
            s[j][2] = fast_exp(s[j][2] - mn1); ps1 += s[j][2];
            s[j][3] = fast_exp(s[j][3] - mn1); ps1 += s[j][3];
        }
        ps0 += __shfl_xor_sync(0xffffffffu, ps0, 1);
        ps0 += __shfl_xor_sync(0xffffffffu, ps0, 2);
        ps1 += __shfl_xor_sync(0xffffffffu, ps1, 1);
        ps1 += __shfl_xor_sync(0xffffffffu, ps1, 2);
        lsum[0] = lsum[0] * al0 + ps0;
        lsum[1] = lsum[1] * al1 + ps1;
        mrow[0] = mn0; mrow[1] = mn1;
#pragma unroll
        for (int nt = 0; nt < 4; nt++) {
            o[nt][0] *= al0; o[nt][1] *= al0;
            o[nt][2] *= al1; o[nt][3] *= al1;
        }

        // ---- O += P V (P from fragments, fp16) ----
#pragma unroll
        for (int ks = 0; ks < 4; ks++) {
            int j0 = 2 * ks, j1 = 2 * ks + 1;
            uint32_t ap[4] = { pkh2(s[j0][0], s[j0][1]), pkh2(s[j0][2], s[j0][3]),
                               pkh2(s[j1][0], s[j1][1]), pkh2(s[j1][2], s[j1][3]) };
#pragma unroll
            for (int half = 0; half < 2; half++) {
                uint32_t v4[4];
                ldsm_x4_t(v4[0], v4[1], v4[2], v4[3],
                          sV + (uint32_t)((ks * 16 + lrow) * AST + half * 16 + lkq * 8) * 2);
                uint32_t bv0[2] = { v4[0], v4[1] }, bv1[2] = { v4[2], v4[3] };
                mma_f16(o[half * 2 + 0], ap, bv0);
                mma_f16(o[half * 2 + 1], ap, bv1);
            }
        }
    }

    // ---- epilogue: write ao ----
    int r = lane >> 2, cp = (lane & 3) * 2;
#pragma unroll
    for (int half = 0; half < 2; half++) {
        int row = wid * 16 + r + half * 8;
        int l = qt * 128 + row;
        float inv = 1.0f / lsum[half];
        size_t base = ((size_t)(l * 64 + n)) * C_ + h * 32;
#pragma unroll
        for (int nt = 0; nt < 4; nt++) {
            float v0 = o[nt][half * 2 + 0] * inv;
            float v1 = o[nt][half * 2 + 1] * inv;
            *(uint32_t*)(g_ao + base + nt * 8 + cp) = pkh2(v0, v1);
        }
    }
}

// ---------------- 6) out-proj (fp16 HMMA) + gated residual ---------------------
__global__ __launch_bounds__(256, 2) void outproj_mma_kernel(const float* __restrict__ bias,
                                                             const float* __restrict__ x,
                                                             float* __restrict__ out) {
    __shared__ GemmSmem sm;
    int m0 = blockIdx.x * 128;
    int n0 = blockIdx.y * 64;
    float acc[4][2][4];
#pragma unroll
    for (int mt = 0; mt < 4; mt++)
#pragma unroll
        for (int nt = 0; nt < 2; nt++)
#pragma unroll
            for (int j = 0; j < 4; j++) acc[mt][nt][j] = 0.f;

    gemm_mainloop(sm, g_ao, g_wout, m0, n0, acc);

    int lane = threadIdx.x & 31, wid = threadIdx.x >> 5;
    int wm = wid & 1, wn = wid >> 1;
    int l = (m0 >> 6) + wm;
    int win = l >> 3, b = l & 7;
    int r = lane >> 2;
#pragma unroll
    for (int mt = 0; mt < 4; mt++) {
#pragma unroll
        for (int nt = 0; nt < 2; nt++) {
            int col = n0 + wn * 16 + nt * 8 + (lane & 3) * 2;
            float2 bi = *(const float2*)&bias[col];
            float ca0 = g_ca[b * C_ + col];
            float ca1 = g_ca[b * C_ + col + 1];
#pragma unroll
            for (int half = 0; half < 2; half++) {
                int wq = mt * 16 + r + half * 8;
                size_t idx0 = (((size_t)(b * C_ + col)) * H_ + win) * W_ + wq;
                size_t idx1 = idx0 + (size_t)H_ * W_;
                out[idx0] = x[idx0] * ca0 + acc[mt][nt][half * 2 + 0] + bi.x;
                out[idx1] = x[idx1] * ca1 + acc[mt][nt][half * 2 + 1] + bi.y;
            }
        }
    }
}

// ---------------- launch --------------------------------------------------------
extern "C" void kernel_launch(void* const* d_in, const int* in_sizes, int n_in,
                              void* d_out, int out_size) {
    const float* x     = (const float*)d_in[0];
    const float* ca_w1 = (const float*)d_in[1];
    const float* ca_b1 = (const float*)d_in[2];
    const float* ca_w2 = (const float*)d_in[3];
    const float* ca_b2 = (const float*)d_in[4];
    const float* in_w  = (const float*)d_in[5];
    const float* in_b  = (const float*)d_in[6];
    const float* out_w = (const float*)d_in[7];
    const float* out_b = (const float*)d_in[8];
    float* out = (float*)d_out;

    int conv_blocks = (3 * C_ * C_ + 255) / 256;
    prep_kernel<<<B_ * C_ + conv_blocks, 256>>>(x, in_w, out_w);
    se_kernel<<<1, 512>>>(ca_w1, ca_b1, ca_w2, ca_b2);
    gather_kernel<<<dim3(64, 8, 8), 256>>>(x);
    qkv_mma_kernel<<<dim3(NTOK / 128, 12), 256>>>(in_b);
    attn_mma_kernel<<<dim3(4, 8, 64), 256>>>();
    outproj_mma_kernel<<<dim3(NTOK / 128, 4), 256>>>(out_b, x, out);
}

// round 8
// speedup vs baseline: 3.2420x; 1.0204x over previous
#include <cuda_runtime.h>
#include <cuda_fp16.h>
#include <cstdint>
#include <math.h>

// Problem constants
#define B_  8
#define C_  256
#define H_  64
#define W_  64
#define CR_ 64
#define L_  512
#define N_  64
#define NH_ 8
#define HD_ 32
#define NTOK (L_ * N_)          // 32768
#define QK_SCALE 0.17677669529663687f  // 1/sqrt(32)

// ---------------- scratch (device globals; no allocations allowed) -------------
__device__ float g_pooled[B_ * C_];
__device__ float g_ca[B_ * C_];
__device__ __align__(16) __half g_xw[NTOK * C_];      // gated tokens [t][c]
__device__ __align__(16) __half g_wqkv[3 * C_ * C_];
__device__ __align__(16) __half g_wout[C_ * C_];
__device__ __align__(16) __half g_q[N_ * NH_ * L_ * HD_];
__device__ __align__(16) __half g_k[N_ * NH_ * L_ * HD_];
__device__ __align__(16) __half g_v[N_ * NH_ * L_ * HD_];
__device__ __align__(16) __half g_ao[NTOK * C_];      // attn out [t][h*32+d]

// ---------------- PTX helpers ---------------------------------------------------
__device__ __forceinline__ uint32_t smem_u32(const void* p) {
    uint32_t a;
    asm("{ .reg .u64 t; cvta.to.shared.u64 t, %1; cvt.u32.u64 %0, t; }" : "=r"(a) : "l"(p));
    return a;
}
__device__ __forceinline__ void ldsm_x4(uint32_t& r0, uint32_t& r1, uint32_t& r2, uint32_t& r3,
                                        uint32_t addr) {
    asm volatile("ldmatrix.sync.aligned.m8n8.x4.shared.b16 {%0,%1,%2,%3}, [%4];"
                 : "=r"(r0), "=r"(r1), "=r"(r2), "=r"(r3) : "r"(addr));
}
__device__ __forceinline__ void ldsm_x4_t(uint32_t& r0, uint32_t& r1, uint32_t& r2, uint32_t& r3,
                                          uint32_t addr) {
    asm volatile("ldmatrix.sync.aligned.m8n8.x4.trans.shared.b16 {%0,%1,%2,%3}, [%4];"
                 : "=r"(r0), "=r"(r1), "=r"(r2), "=r"(r3) : "r"(addr));
}
__device__ __forceinline__ void mma_f16(float* c, const uint32_t* a, const uint32_t* b) {
    asm volatile("mma.sync.aligned.m16n8k16.row.col.f32.f16.f16.f32 "
                 "{%0,%1,%2,%3}, {%4,%5,%6,%7}, {%8,%9}, {%0,%1,%2,%3};"
                 : "+f"(c[0]), "+f"(c[1]), "+f"(c[2]), "+f"(c[3])
                 : "r"(a[0]), "r"(a[1]), "r"(a[2]), "r"(a[3]), "r"(b[0]), "r"(b[1]));
}
__device__ __forceinline__ void cp16(uint32_t saddr, const void* g) {
    asm volatile("cp.async.cg.shared.global [%0], [%1], 16;" :: "r"(saddr), "l"(g));
}
#define CP_COMMIT() asm volatile("cp.async.commit_group;" ::: "memory")
#define CP_WAIT0()  asm volatile("cp.async.wait_group 0;" ::: "memory")

#define BK 32
#define AST 40   // padded smem row stride in halfs (80B: conflict-free ldmatrix)

// ---------------- fast exp on FMA/ALU pipes -------------------------------------
__device__ __forceinline__ float fast_exp(float x) {
    x = fmaxf(x, -87.0f);
    float y = x * 1.44269504088896341f;
    float n = rintf(y);
    float f = y - n;
    float t = f * 0.6931471805599453f;
    float p = 1.0f + t * (1.0f + t * (0.5f + t * (0.16666667f + t * (0.041666668f + t * 0.008333334f))));
    int e = (int)n;
    float s = __int_as_float((e + 127) << 23);
    return p * s;
}
__device__ __forceinline__ uint32_t pkh2(float a, float b) {
    __half2 t = __floats2half2_rn(a, b);
    return *reinterpret_cast<uint32_t*>(&t);
}

// ---------------- 1) merged prep: pool (blocks 0..2047) + W convert -------------
__global__ void prep_kernel(const float* __restrict__ x,
                            const float* __restrict__ in_w, const float* __restrict__ out_w) {
    int bid = blockIdx.x;
    if (bid < B_ * C_) {
        const float* p = x + (size_t)bid * (H_ * W_);
        float s = 0.f;
        for (int i = threadIdx.x; i < H_ * W_; i += 256) s += p[i];
        __shared__ float red[8];
        for (int o = 16; o; o >>= 1) s += __shfl_xor_sync(0xffffffffu, s, o);
        if ((threadIdx.x & 31) == 0) red[threadIdx.x >> 5] = s;
        __syncthreads();
        if (threadIdx.x < 8) {
            s = red[threadIdx.x];
            for (int o = 4; o; o >>= 1) s += __shfl_xor_sync(0xffu, s, o);
            if (threadIdx.x == 0) g_pooled[bid] = s * (1.0f / (H_ * W_));
        }
    } else {
        int i = (bid - B_ * C_) * 256 + threadIdx.x;
        if (i < 3 * C_ * C_) g_wqkv[i] = __float2half_rn(in_w[i]);
        if (i < C_ * C_)     g_wout[i] = __float2half_rn(out_w[i]);
    }
}

// ---------------- 2) SE gate MLP -----------------------------------------------
__global__ void se_kernel(const float* __restrict__ w1, const float* __restrict__ b1,
                          const float* __restrict__ w2, const float* __restrict__ b2) {
    __shared__ float h1s[B_ * CR_];
    int tid = threadIdx.x;
    {
        int b = tid >> 6, j = tid & 63;
        float s = b1[j];
        const float* pw = w1 + j * C_;
        const float* pp = g_pooled + b * C_;
        for (int c = 0; c < C_; c++) s += pp[c] * pw[c];
        h1s[tid] = fmaxf(s, 0.f);
    }
    __syncthreads();
    for (int i = tid; i < B_ * C_; i += 512) {
        int b = i >> 8, c = i & 255;
        float s = b2[c];
        const float* pw = w2 + c * CR_;
        const float* ph = h1s + b * CR_;
        for (int j = 0; j < CR_; j++) s += ph[j] * pw[j];
        g_ca[i] = 1.0f / (1.0f + expf(-s));
    }
}

// ---------------- 3) gather gated windows into fp16 token matrix ---------------
__global__ void gather_kernel(const float* __restrict__ x) {
    int hp = blockIdx.x;
    int cg = blockIdx.y;
    int b  = blockIdx.z;
    __shared__ float tile[32][65];
    int tid = threadIdx.x;
    int wp = tid & 63, ci = tid >> 6;
    const float* base = x + (((size_t)(b * C_ + cg * 32)) << 12) + hp * W_;
#pragma unroll
    for (int i = 0; i < 8; i++) {
        int c = ci + i * 4;
        tile[c][wp] = base[((size_t)c << 12) + wp];
    }
    __syncthreads();
    int j = tid & 31, pi = tid >> 5;
    int hw = hp >> 3, r = hp & 7;
    float cav = g_ca[b * C_ + cg * 32 + j];
#pragma unroll
    for (int i = 0; i < 8; i++) {
        int wpp = pi + i * 8;
        int ww = wpp >> 3, cc = wpp & 7;
        int l = (hw * 8 + ww) * 8 + b;
        int t = l * 64 + (r * 8 + cc);
        g_xw[(size_t)t * C_ + cg * 32 + j] = __float2half_rn(tile[j][wpp] * cav);
    }
}

// ---------------- shared mainloop: fp16 HMMA GEMM 128x128, cp.async 2-stage ----
struct GemmSmem {
    __half A[2][128][AST];
    __half Bm[2][128][AST];
};

__device__ __forceinline__ void gemm_load_chunk(GemmSmem& sm, int buf,
    const __half* __restrict__ A, const __half* __restrict__ Bm,
    int m0, int n0, int k0, int tid) {
#pragma unroll
    for (int p = 0; p < 2; p++) {
        int i = tid + p * 256;
        int row = i >> 2, q = i & 3;
        cp16(smem_u32(&sm.A[buf][row][q * 8]), A + (size_t)(m0 + row) * C_ + k0 + q * 8);
        cp16(smem_u32(&sm.Bm[buf][row][q * 8]), Bm + (size_t)(n0 + row) * C_ + k0 + q * 8);
    }
    CP_COMMIT();
}

// 8 warps as 2(M) x 4(N); warp tile 64 x 32; acc[mt 0..3][nt 0..3][4]
__device__ __forceinline__ void gemm_mainloop(GemmSmem& sm,
    const __half* __restrict__ A, const __half* __restrict__ Bm,
    int m0, int n0, float acc[4][4][4]) {
    int tid = threadIdx.x;
    int lane = tid & 31, wid = tid >> 5;
    int wm = wid & 1, wn = wid >> 1;
    int lrow = lane & 15, lkq = lane >> 4;

    gemm_load_chunk(sm, 0, A, Bm, m0, n0, 0, tid);

    for (int chunk = 0; chunk < 8; chunk++) {
        int buf = chunk & 1;
        CP_WAIT0();
        __syncthreads();
        if (chunk < 7)
            gemm_load_chunk(sm, buf ^ 1, A, Bm, m0, n0, (chunk + 1) * BK, tid);

        uint32_t sA0 = smem_u32(&sm.A[buf][0][0]);
        uint32_t sB0 = smem_u32(&sm.Bm[buf][0][0]);
#pragma unroll
        for (int ks = 0; ks < 2; ks++) {
            int kk = ks * 16 + lkq * 8;
            uint32_t a4[4][4], bA[4], bB[4];
#pragma unroll
            for (int mt = 0; mt < 4; mt++) {
                int row = wm * 64 + mt * 16 + lrow;
                ldsm_x4(a4[mt][0], a4[mt][1], a4[mt][2], a4[mt][3],
                        sA0 + (uint32_t)(row * AST + kk) * 2);
            }
            ldsm_x4(bA[0], bA[1], bA[2], bA[3],
                    sB0 + (uint32_t)((wn * 32 + lrow) * AST + kk) * 2);
            ldsm_x4(bB[0], bB[1], bB[2], bB[3],
                    sB0 + (uint32_t)((wn * 32 + 16 + lrow) * AST + kk) * 2);
            uint32_t b0[2] = { bA[0], bA[2] }, b1[2] = { bA[1], bA[3] };
            uint32_t b2[2] = { bB[0], bB[2] }, b3[2] = { bB[1], bB[3] };
#pragma unroll
            for (int mt = 0; mt < 4; mt++) {
                mma_f16(acc[mt][0], a4[mt], b0);
                mma_f16(acc[mt][1], a4[mt], b1);
                mma_f16(acc[mt][2], a4[mt], b2);
                mma_f16(acc[mt][3], a4[mt], b3);
            }
        }
    }
}

// ---------------- 4) QKV projection (fp16 HMMA) --------------------------------
__global__ __launch_bounds__(256, 2) void qkv_mma_kernel(const float* __restrict__ bias) {
    __shared__ GemmSmem sm;
    int m0 = blockIdx.x * 128;
    int n0 = blockIdx.y * 128;
    float acc[4][4][4];
#pragma unroll
    for (int mt = 0; mt < 4; mt++)
#pragma unroll
        for (int nt = 0; nt < 4; nt++)
#pragma unroll
            for (int j = 0; j < 4; j++) acc[mt][nt][j] = 0.f;

    gemm_mainloop(sm, g_xw, g_wqkv, m0, n0, acc);

    int lane = threadIdx.x & 31, wid = threadIdx.x >> 5;
    int wm = wid & 1, wn = wid >> 1;
    int sec = n0 >> 8;                 // 0=Q, 1=K, 2=V
    __half* dst = (sec == 0) ? g_q : (sec == 1) ? g_k : g_v;
    float scale = (sec == 0) ? QK_SCALE : 1.0f;
    int l = (m0 >> 6) + wm;
    int r = lane >> 2;
#pragma unroll
    for (int mt = 0; mt < 4; mt++) {
#pragma unroll
        for (int nt = 0; nt < 4; nt++) {
            int col = n0 + wn * 32 + nt * 8 + (lane & 3) * 2;
            int oc = col & 255;
            int h = oc >> 5, d = oc & 31;
            float2 bi = *(const float2*)&bias[col];
#pragma unroll
            for (int half = 0; half < 2; half++) {
                int n = mt * 16 + r + half * 8;
                float v0 = (acc[mt][nt][half * 2 + 0] + bi.x) * scale;
                float v1 = (acc[mt][nt][half * 2 + 1] + bi.y) * scale;
                size_t idx = (((size_t)(n * NH_ + h) * L_ + l) << 5) + d;
                *(uint32_t*)(dst + idx) = pkh2(v0, v1);
            }
        }
    }
}

// ---------------- 5) attention (fp16 HMMA flash, S/softmax overlap) ------------
__device__ __forceinline__ void attn_compute_S(float s[8][4], uint32_t sQ, uint32_t sK,
                                               int wid, int lrow, int lkq) {
#pragma unroll
    for (int j = 0; j < 8; j++)
#pragma unroll
        for (int c = 0; c < 4; c++) s[j][c] = 0.f;
#pragma unroll
    for (int ks = 0; ks < 2; ks++) {
        int kk = ks * 16 + lkq * 8;
        uint32_t aq[4];
        ldsm_x4(aq[0], aq[1], aq[2], aq[3],
                sQ + (uint32_t)((wid * 16 + lrow) * AST + kk) * 2);
#pragma unroll
        for (int j = 0; j < 4; j++) {
            uint32_t b4[4];
            ldsm_x4(b4[0], b4[1], b4[2], b4[3],
                    sK + (uint32_t)((j * 16 + lrow) * AST + kk) * 2);
            uint32_t b0[2] = { b4[0], b4[2] }, b1[2] = { b4[1], b4[3] };
            mma_f16(s[2 * j + 0], aq, b0);
            mma_f16(s[2 * j + 1], aq, b1);
        }
    }
}

__global__ __launch_bounds__(256, 2) void attn_mma_kernel() {
    int qt = blockIdx.x;   // 0..3
    int h  = blockIdx.y;   // 0..7
    int n  = blockIdx.z;   // 0..63
    __shared__ __half Qs[128][AST];
    __shared__ __half Ks[2][64][AST];
    __shared__ __half Vs[2][64][AST];

    size_t head = ((size_t)(n * NH_ + h)) * L_ * HD_;
    const __half* qg = g_q + head;
    const __half* kg = g_k + head;
    const __half* vg = g_v + head;

    int tid = threadIdx.x;
    int lane = tid & 31, wid = tid >> 5;
    int kvrow = tid >> 2, kvq = tid & 3;
    int lrow = lane & 15, lkq = lane >> 4;

    // prologue: K0+V0 (group), K1 (group), Q plain
    {
        size_t gi = (size_t)kvrow * HD_ + kvq * 8;
        cp16(smem_u32(&Ks[0][kvrow][kvq * 8]), kg + gi);
        cp16(smem_u32(&Vs[0][kvrow][kvq * 8]), vg + gi);
        CP_COMMIT();
        cp16(smem_u32(&Ks[1][kvrow][kvq * 8]), kg + (size_t)(64 + kvrow) * HD_ + kvq * 8);
        CP_COMMIT();
    }
#pragma unroll
    for (int p = 0; p < 2; p++) {
        int i = tid + p * 256;
        int row = i >> 2, q = i & 3;
        *(uint4*)&Qs[row][q * 8] = *(const uint4*)(qg + (size_t)(qt * 128 + row) * HD_ + q * 8);
    }
    uint32_t sQ = smem_u32(&Qs[0][0]);

    CP_WAIT0();
    __syncthreads();

    float s[2][8][4];
    attn_compute_S(s[0], sQ, smem_u32(&Ks[0][0][0]), wid, lrow, lkq);
    __syncthreads();   // protect Ks[0] from kt=0's K2 prefetch overwrite

    float o[4][4];
#pragma unroll
    for (int i = 0; i < 4; i++)
#pragma unroll
        for (int j = 0; j < 4; j++) o[i][j] = 0.f;
    float mrow[2] = { -1e30f, -1e30f };
    float lsum[2] = { 0.f, 0.f };

#pragma unroll 2
    for (int kt = 0; kt < 8; kt++) {
        const int cur = kt & 1, nxt = cur ^ 1;
        // prefetch K(kt+2) -> Ks[cur] (K(kt) is dead), V(kt+1) -> Vs[nxt]
        if (kt < 6)
            cp16(smem_u32(&Ks[cur][kvrow][kvq * 8]),
                 kg + (size_t)((kt + 2) * 64 + kvrow) * HD_ + kvq * 8);
        if (kt < 7) {
            cp16(smem_u32(&Vs[nxt][kvrow][kvq * 8]),
                 vg + (size_t)((kt + 1) * 64 + kvrow) * HD_ + kvq * 8);
            CP_COMMIT();
            // S(kt+1): independent MMA stream, overlaps the softmax FMA stream below
            attn_compute_S(s[nxt], sQ, smem_u32(&Ks[nxt][0][0]), wid, lrow, lkq);
        }

        // ---- online softmax on s[cur] ----
        float (*sc)[4] = s[cur];
        float mx0 = -1e30f, mx1 = -1e30f;
#pragma unroll
        for (int j = 0; j < 8; j++) {
            mx0 = fmaxf(mx0, fmaxf(sc[j][0], sc[j][1]));
            mx1 = fmaxf(mx1, fmaxf(sc[j][2], sc[j][3]));
        }
        mx0 = fmaxf(mx0, __shfl_xor_sync(0xffffffffu, mx0, 1));
        mx0 = fmaxf(mx0, __shfl_xor_sync(0xffffffffu, mx0, 2));
        mx1 = fmaxf(mx1, __shfl_xor_sync(0xffffffffu, mx1, 1));
        mx1 = fmaxf(mx1, __shfl_xor_sync(0xffffffffu, mx1, 2));
        float mn0 = fmaxf(mrow[0], mx0), mn1 = fmaxf(mrow[1], mx1);
        float al0 = fast_exp(mrow[0] - mn0), al1 = fast_exp(mrow[1] - mn1);
        float ps0 = 0.f, ps1 = 0.f;
#pragma unroll
        for (int j = 0; j < 8; j++) {
            sc[j][0] = fast_exp(sc[j][0] - mn0); ps0 += sc[j][0];
            sc[j][1] = fast_exp(sc[j][1] - mn0); ps0 += sc[j][1];
            sc[j][2] = fast_exp(sc[j][2] - mn1); ps1 += sc[j][2];
            sc[j][3] = fast_exp(sc[j][3] - mn1); ps1 += sc[j][3];
        }
        // deferred: per-thread partial row sums; cross-lane reduce once at end
        lsum[0] = lsum[0] * al0 + ps0;
        lsum[1] = lsum[1] * al1 + ps1;
        mrow[0] = mn0; mrow[1] = mn1;
#pragma unroll
        for (int nt = 0; nt < 4; nt++) {
            o[nt][0] *= al0; o[nt][1] *= al0;
            o[nt][2] *= al1; o[nt][3] *= al1;
        }

        // ---- O += P V ----
        uint32_t sV = smem_u32(&Vs[cur][0][0]);
#pragma unroll
        for (int ks = 0; ks < 4; ks++) {
            int j0 = 2 * ks, j1 = 2 * ks + 1;
            uint32_t ap[4] = { pkh2(sc[j0][0], sc[j0][1]), pkh2(sc[j0][2], sc[j0][3]),
                               pkh2(sc[j1][0], sc[j1][1]), pkh2(sc[j1][2], sc[j1][3]) };
#pragma unroll
            for (int half = 0; half < 2; half++) {
                uint32_t v4[4];
                ldsm_x4_t(v4[0], v4[1], v4[2], v4[3],
                          sV + (uint32_t)((ks * 16 + lrow) * AST + half * 16 + lkq * 8) * 2);
                uint32_t bv0[2] = { v4[0], v4[1] }, bv1[2] = { v4[2], v4[3] };
                mma_f16(o[half * 2 + 0], ap, bv0);
                mma_f16(o[half * 2 + 1], ap, bv1);
            }
        }
        if (kt < 7) {
            CP_WAIT0();
            __syncthreads();
        }
    }

    // ---- epilogue: final lsum reduction + write ao ----
    lsum[0] += __shfl_xor_sync(0xffffffffu, lsum[0], 1);
    lsum[0] += __shfl_xor_sync(0xffffffffu, lsum[0], 2);
    lsum[1] += __shfl_xor_sync(0xffffffffu, lsum[1], 1);
    lsum[1] += __shfl_xor_sync(0xffffffffu, lsum[1], 2);
    int r = lane >> 2, cp = (lane & 3) * 2;
#pragma unroll
    for (int half = 0; half < 2; half++) {
        int row = wid * 16 + r + half * 8;
        int l = qt * 128 + row;
        float inv = 1.0f / lsum[half];
        size_t base = ((size_t)(l * 64 + n)) * C_ + h * 32;
#pragma unroll
        for (int nt = 0; nt < 4; nt++) {
            float v0 = o[nt][half * 2 + 0] * inv;
            float v1 = o[nt][half * 2 + 1] * inv;
            *(uint32_t*)(g_ao + base + nt * 8 + cp) = pkh2(v0, v1);
        }
    }
}

// ---------------- 6) out-proj (fp16 HMMA) + gated residual ---------------------
__global__ __launch_bounds__(256, 2) void outproj_mma_kernel(const float* __restrict__ bias,
                                                             const float* __restrict__ x,
                                                             float* __restrict__ out) {
    __shared__ GemmSmem sm;
    int m0 = blockIdx.x * 128;
    int n0 = blockIdx.y * 128;
    float acc[4][4][4];
#pragma unroll
    for (int mt = 0; mt < 4; mt++)
#pragma unroll
        for (int nt = 0; nt < 4; nt++)
#pragma unroll
            for (int j = 0; j < 4; j++) acc[mt][nt][j] = 0.f;

    gemm_mainloop(sm, g_ao, g_wout, m0, n0, acc);

    int lane = threadIdx.x & 31, wid = threadIdx.x >> 5;
    int wm = wid & 1, wn = wid >> 1;
    int l = (m0 >> 6) + wm;
    int win = l >> 3, b = l & 7;
    int r = lane >> 2;
#pragma unroll
    for (int mt = 0; mt < 4; mt++) {
#pragma unroll
        for (int nt = 0; nt < 4; nt++) {
            int col = n0 + wn * 32 + nt * 8 + (lane & 3) * 2;
            float2 bi = *(const float2*)&bias[col];
            float ca0 = g_ca[b * C_ + col];
            float ca1 = g_ca[b * C_ + col + 1];
#pragma unroll
            for (int half = 0; half < 2; half++) {
                int wq = mt * 16 + r + half * 8;
                size_t idx0 = (((size_t)(b * C_ + col)) * H_ + win) * W_ + wq;
                size_t idx1 = idx0 + (size_t)H_ * W_;
                out[idx0] = x[idx0] * ca0 + acc[mt][nt][half * 2 + 0] + bi.x;
                out[idx1] = x[idx1] * ca1 + acc[mt][nt][half * 2 + 1] + bi.y;
            }
        }
    }
}

// ---------------- launch --------------------------------------------------------
extern "C" void kernel_launch(void* const* d_in, const int* in_sizes, int n_in,
                              void* d_out, int out_size) {
    const float* x     = (const float*)d_in[0];
    const float* ca_w1 = (const float*)d_in[1];
    const float* ca_b1 = (const float*)d_in[2];
    const float* ca_w2 = (const float*)d_in[3];
    const float* ca_b2 = (const float*)d_in[4];
    const float* in_w  = (const float*)d_in[5];
    const float* in_b  = (const float*)d_in[6];
    const float* out_w = (const float*)d_in[7];
    const float* out_b = (const float*)d_in[8];
    float* out = (float*)d_out;

    int conv_blocks = (3 * C_ * C_ + 255) / 256;
    prep_kernel<<<B_ * C_ + conv_blocks, 256>>>(x, in_w, out_w);
    se_kernel<<<1, 512>>>(ca_w1, ca_b1, ca_w2, ca_b2);
    gather_kernel<<<dim3(64, 8, 8), 256>>>(x);
    qkv_mma_kernel<<<dim3(NTOK / 128, 6), 256>>>(in_b);
    attn_mma_kernel<<<dim3(4, 8, 64), 256>>>();
    outproj_mma_kernel<<<dim3(NTOK / 128, 2), 256>>>(out_b, x, out);
}